// round 2
// baseline (speedup 1.0000x reference)
#include <cuda_runtime.h>
#include <math.h>

#define BB   2
#define NSEQ 2048
#define DIMM 1536
#define HH   8
#define DKK  64
#define DVV  64
#define NRPF 192
#define NB   32
#define NPOS 4095          // 2N-1
#define BN   4096          // B*N
#define HD   512           // H*DK

// -------- scratch (device globals; no allocation allowed) --------
__device__ float g_p[NPOS * NB];                       // gamma pdf values
__device__ float g_pmax;
__device__ float g_emb[NPOS * NRPF];                   // positional basis
__device__ float g_pos[NPOS * HD];                     // emb @ Wrel  [4095][512]
__device__ float g_qc[BB * HH * NSEQ * DKK];           // q*scale + content bias
__device__ float g_qp[BB * HH * NSEQ * DKK];           // q*scale + pos bias
__device__ float g_k [BB * HH * NSEQ * DKK];
__device__ float g_v [BB * HH * NSEQ * DVV];
__device__ float g_logits[(size_t)BB * HH * NSEQ * NSEQ];  // 268 MB
__device__ float g_ao[(size_t)BN * (HH * DVV)];        // attn@v, [B*N][512]

// ---------------- positional basis ----------------
__global__ void init_kernel() { g_pmax = 0.0f; }

__global__ void gamma_kernel() {
    int idx = blockIdx.x * blockDim.x + threadIdx.x;
    float p = 0.0f;
    if (idx < NPOS * NB) {
        int row = idx / NB;
        int j   = idx - row * NB;
        double ad   = (double)abs(row - (NSEQ - 1));
        double mean = 64.0 * (double)(j + 1);          // linspace(64,2048,32)
        double conc = (mean / 32.0) * (mean / 32.0);
        double rate = mean / 1024.0;
        double xl   = (ad > 0.0) ? (conc - 1.0) * log(ad) : 0.0;  // xlogy
        double logp = xl - rate * ad - (lgamma(conc) - conc * log(rate));
        p = (float)exp(logp) + 1e-8f;
        g_p[idx] = p;
    }
    __shared__ float red[256];
    red[threadIdx.x] = p;
    __syncthreads();
    for (int s = 128; s > 0; s >>= 1) {
        if (threadIdx.x < s) red[threadIdx.x] = fmaxf(red[threadIdx.x], red[threadIdx.x + s]);
        __syncthreads();
    }
    if (threadIdx.x == 0) atomicMax((int*)&g_pmax, __float_as_int(red[0]));
}

__global__ void emb_kernel() {
    int row = blockIdx.x;          // 0..4094
    int t   = threadIdx.x;         // 0..95
    int d   = row - (NSEQ - 1);
    float ad = fabsf((float)d);
    float sg = (d > 0) ? 1.0f : ((d < 0) ? -1.0f : 0.0f);
    float f;
    if (t < NB) {
        // exponential: 2^(-ad/half_life), half_life = 2^linspace(3, log2(N), 32)
        double maxr = log((double)NSEQ) / log(2.0);
        double xh   = 3.0 + (double)t * (maxr - 3.0) / (double)(NB - 1);
        double hl   = exp2(xh);
        f = (float)exp(-0.6931471805599453 / hl * (double)ad);
    } else if (t < 2 * NB) {
        int jj = t - NB;
        float width = exp2f((float)(jj + 1)) - 1.0f;
        f = (width > ad) ? 1.0f : 0.0f;
    } else {
        f = g_p[row * NB + (t - 2 * NB)] / g_pmax;
    }
    g_emb[row * NRPF + t]      = f;
    g_emb[row * NRPF + 96 + t] = sg * f;
}

// ---------------- generic tiled SGEMM (64x64 tile, 4x4/thread) ----------------
// mode 0: C[r*Nc+c] = acc                              (pos projection)
// mode 1: qc/qp epilogue (Q): scale + biases, BHND layout
// mode 2: BHND layout write to C                       (K / V)
// mode 3: C[r*Nc+c] = acc + bias1[c]                   (final projection)
__global__ __launch_bounds__(256) void sgemm_kernel(
    const float* __restrict__ A, const float* __restrict__ B, float* __restrict__ C,
    int M, int Nc, int K, int mode,
    const float* __restrict__ bias1, const float* __restrict__ bias2)
{
    __shared__ float As[64][17];
    __shared__ float Bs[16][68];
    int tid = threadIdx.x;
    int tx = tid & 15, ty = tid >> 4;
    int j0 = blockIdx.x * 64, i0 = blockIdx.y * 64;
    float acc[4][4] = {};

    for (int k0 = 0; k0 < K; k0 += 16) {
        {   // A tile: 64 x 16
            int r = tid >> 2, c4 = (tid & 3) * 4;
            int gr = i0 + r;
            float4 v = make_float4(0.f, 0.f, 0.f, 0.f);
            if (gr < M) v = *(const float4*)&A[(size_t)gr * K + k0 + c4];
            As[r][c4] = v.x; As[r][c4 + 1] = v.y; As[r][c4 + 2] = v.z; As[r][c4 + 3] = v.w;
        }
        {   // B tile: 16 x 64
            int r = tid >> 4, c4 = (tid & 15) * 4;
            *(float4*)&Bs[r][c4] = *(const float4*)&B[(size_t)(k0 + r) * Nc + j0 + c4];
        }
        __syncthreads();
#pragma unroll
        for (int kk = 0; kk < 16; kk++) {
            float a[4];
#pragma unroll
            for (int ii = 0; ii < 4; ii++) a[ii] = As[ty * 4 + ii][kk];
            float4 bv = *(float4*)&Bs[kk][tx * 4];
            float b[4] = {bv.x, bv.y, bv.z, bv.w};
#pragma unroll
            for (int ii = 0; ii < 4; ii++)
#pragma unroll
                for (int jj = 0; jj < 4; jj++)
                    acc[ii][jj] += a[ii] * b[jj];
        }
        __syncthreads();
    }

#pragma unroll
    for (int ii = 0; ii < 4; ii++) {
        int gr = i0 + ty * 4 + ii;
        if (gr >= M) continue;
#pragma unroll
        for (int jj = 0; jj < 4; jj++) {
            int gc = j0 + tx * 4 + jj;
            float val = acc[ii][jj];
            if (mode == 0) {
                C[(size_t)gr * Nc + gc] = val;
            } else if (mode == 1) {
                int b = gr >> 11, n = gr & 2047;
                int h = gc >> 6,  dk = gc & 63;
                size_t dst = (((size_t)(b * HH + h)) * NSEQ + n) * DKK + dk;
                float q = val * 0.125f;               // DK^-0.5
                g_qc[dst] = q + bias1[gc];
                g_qp[dst] = q + bias2[gc];
            } else if (mode == 2) {
                int b = gr >> 11, n = gr & 2047;
                int h = gc >> 6,  dk = gc & 63;
                C[(((size_t)(b * HH + h)) * NSEQ + n) * DKK + dk] = val;
            } else {
                C[(size_t)gr * Nc + gc] = val + bias1[gc];
            }
        }
    }
}

// ---------------- fused logits: content + shifted relative ----------------
// logits[b,h,i,j] = qc_i . k_j  +  qp_i . pos[(N-1)+j-i]
__global__ __launch_bounds__(256) void logits_kernel() {
    extern __shared__ float sm[];
    float* qcs  = sm;                    // 64 x 68
    float* qps  = sm + 64 * 68;
    float* ks   = sm + 2 * 64 * 68;
    float* poss = sm + 3 * 64 * 68;      // 127 x 68

    int bh = blockIdx.z;
    int h  = bh & 7;
    int i0 = blockIdx.y * 64, j0 = blockIdx.x * 64;
    int tid = threadIdx.x;
    int tx = tid & 15, ty = tid >> 4;

    const float* qcg = g_qc + ((size_t)bh * NSEQ + i0) * DKK;
    const float* qpg = g_qp + ((size_t)bh * NSEQ + i0) * DKK;
    const float* kg  = g_k  + ((size_t)bh * NSEQ + j0) * DKK;
#pragma unroll
    for (int t = 0; t < 4; t++) {
        int idx = tid + t * 256;                  // 1024 float4 per tile
        int r = idx >> 4, c4 = (idx & 15) * 4;
        *(float4*)&qcs[r * 68 + c4] = *(const float4*)&qcg[r * 64 + c4];
        *(float4*)&qps[r * 68 + c4] = *(const float4*)&qpg[r * 64 + c4];
        *(float4*)&ks [r * 68 + c4] = *(const float4*)&kg [r * 64 + c4];
    }
    // pos band: 127 rows x 64 cols, global rows rbase..rbase+126 (always in range)
    int rbase = (NSEQ - 1) + j0 - i0 - 63;
    const float* pg = g_pos + (size_t)rbase * HD + h * 64;
#pragma unroll
    for (int t = 0; t < 8; t++) {
        int idx = tid + t * 256;
        if (idx < 127 * 16) {
            int r = idx >> 4, c4 = (idx & 15) * 4;
            *(float4*)&poss[r * 68 + c4] = *(const float4*)&pg[(size_t)r * HD + c4];
        }
    }
    __syncthreads();

    float acc[4][4] = {};
    int prow0 = 60 + 4 * tx - 4 * ty;     // pos row for (jj-ii) = -3
#pragma unroll
    for (int kk4 = 0; kk4 < 16; kk4++) {
        int kc = kk4 * 4;
        float4 kv[4], pv[7];
#pragma unroll
        for (int jj = 0; jj < 4; jj++) kv[jj] = *(float4*)&ks[(tx * 4 + jj) * 68 + kc];
#pragma unroll
        for (int t = 0; t < 7; t++)  pv[t]  = *(float4*)&poss[(prow0 + t) * 68 + kc];
#pragma unroll
        for (int ii = 0; ii < 4; ii++) {
            float4 qa = *(float4*)&qcs[(ty * 4 + ii) * 68 + kc];
            float4 qb = *(float4*)&qps[(ty * 4 + ii) * 68 + kc];
#pragma unroll
            for (int jj = 0; jj < 4; jj++) {
                float4 kvj = kv[jj];
                float4 pvj = pv[jj - ii + 3];
                acc[ii][jj] += qa.x * kvj.x + qa.y * kvj.y + qa.z * kvj.z + qa.w * kvj.w
                             + qb.x * pvj.x + qb.y * pvj.y + qb.z * pvj.z + qb.w * pvj.w;
            }
        }
    }

    size_t obase = ((size_t)bh * NSEQ + i0) * NSEQ + j0;
#pragma unroll
    for (int ii = 0; ii < 4; ii++) {
        float4 o = make_float4(acc[ii][0], acc[ii][1], acc[ii][2], acc[ii][3]);
        *(float4*)&g_logits[obase + (size_t)(ty * 4 + ii) * NSEQ + tx * 4] = o;
    }
}

// ---------------- softmax over rows of length 2048 ----------------
__global__ __launch_bounds__(128) void softmax_kernel() {
    int row = blockIdx.x;
    float* p = g_logits + (size_t)row * NSEQ;
    int tid = threadIdx.x;
    float v[16];
    float m = -1e30f;
#pragma unroll
    for (int e = 0; e < 16; e++) { v[e] = p[tid + e * 128]; m = fmaxf(m, v[e]); }
    __shared__ float red[128];
    red[tid] = m; __syncthreads();
    for (int s = 64; s > 0; s >>= 1) {
        if (tid < s) red[tid] = fmaxf(red[tid], red[tid + s]);
        __syncthreads();
    }
    m = red[0]; __syncthreads();
    float sum = 0.f;
#pragma unroll
    for (int e = 0; e < 16; e++) { v[e] = expf(v[e] - m); sum += v[e]; }
    red[tid] = sum; __syncthreads();
    for (int s = 64; s > 0; s >>= 1) {
        if (tid < s) red[tid] += red[tid + s];
        __syncthreads();
    }
    float inv = 1.0f / red[0];
#pragma unroll
    for (int e = 0; e < 16; e++) p[tid + e * 128] = v[e] * inv;
}

// ---------------- attn @ v ----------------
__global__ __launch_bounds__(256) void av_kernel() {
    __shared__ float As[64][17];
    __shared__ float Bs[16][68];
    int bh = blockIdx.y;
    int i0 = blockIdx.x * 64;
    const float* A = g_logits + (size_t)bh * NSEQ * NSEQ;
    const float* V = g_v + (size_t)bh * NSEQ * DVV;
    int tid = threadIdx.x;
    int tx = tid & 15, ty = tid >> 4;
    float acc[4][4] = {};

    for (int k0 = 0; k0 < NSEQ; k0 += 16) {
        {
            int r = tid >> 2, c4 = (tid & 3) * 4;
            float4 v = *(const float4*)&A[(size_t)(i0 + r) * NSEQ + k0 + c4];
            As[r][c4] = v.x; As[r][c4 + 1] = v.y; As[r][c4 + 2] = v.z; As[r][c4 + 3] = v.w;
        }
        {
            int r = tid >> 4, c4 = (tid & 15) * 4;
            *(float4*)&Bs[r][c4] = *(const float4*)&V[(size_t)(k0 + r) * DVV + c4];
        }
        __syncthreads();
#pragma unroll
        for (int kk = 0; kk < 16; kk++) {
            float a[4];
#pragma unroll
            for (int ii = 0; ii < 4; ii++) a[ii] = As[ty * 4 + ii][kk];
            float4 bv = *(float4*)&Bs[kk][tx * 4];
            float b[4] = {bv.x, bv.y, bv.z, bv.w};
#pragma unroll
            for (int ii = 0; ii < 4; ii++)
#pragma unroll
                for (int jj = 0; jj < 4; jj++)
                    acc[ii][jj] += a[ii] * b[jj];
        }
        __syncthreads();
    }

    int b = bh >> 3, h = bh & 7;
#pragma unroll
    for (int ii = 0; ii < 4; ii++) {
        int n = i0 + ty * 4 + ii;
        float4 o = make_float4(acc[ii][0], acc[ii][1], acc[ii][2], acc[ii][3]);
        *(float4*)&g_ao[((size_t)(b * NSEQ + n)) * HD + h * 64 + tx * 4] = o;
    }
}

// ---------------- launch ----------------
extern "C" void kernel_launch(void* const* d_in, const int* in_sizes, int n_in,
                              void* d_out, int out_size) {
    const float* x    = (const float*)d_in[0];
    const float* Wq   = (const float*)d_in[1];
    const float* Wk   = (const float*)d_in[2];
    const float* Wv   = (const float*)d_in[3];
    const float* Wo   = (const float*)d_in[4];
    const float* bo   = (const float*)d_in[5];
    const float* Wrel = (const float*)d_in[6];
    const float* cb   = (const float*)d_in[7];  // rel_content_bias [H*DK]
    const float* pb   = (const float*)d_in[8];  // rel_pos_bias     [H*DK]
    float* out = (float*)d_out;

    const int LOGITS_SMEM = (3 * 64 + 127) * 68 * 4;  // 86768 bytes
    cudaFuncSetAttribute(logits_kernel, cudaFuncAttributeMaxDynamicSharedMemorySize, LOGITS_SMEM);

    // positional basis
    init_kernel<<<1, 1>>>();
    gamma_kernel<<<(NPOS * NB + 255) / 256, 256>>>();
    emb_kernel<<<NPOS, 96>>>();

    // pos = emb @ Wrel    [4095 x 512]
    {
        float* posp = nullptr; cudaGetSymbolAddress((void**)&posp, g_pos);
        float* embp = nullptr; cudaGetSymbolAddress((void**)&embp, g_emb);
        sgemm_kernel<<<dim3(HD / 64, (NPOS + 63) / 64), 256>>>(
            embp, Wrel, posp, NPOS, HD, NRPF, 0, nullptr, nullptr);
    }

    // q/k/v projections (4096 x 512, K=1536)
    {
        float* qcp = nullptr; cudaGetSymbolAddress((void**)&qcp, g_qc);
        float* kp  = nullptr; cudaGetSymbolAddress((void**)&kp, g_k);
        float* vp  = nullptr; cudaGetSymbolAddress((void**)&vp, g_v);
        sgemm_kernel<<<dim3(HD / 64, BN / 64), 256>>>(x, Wq, qcp, BN, HD, DIMM, 1, cb, pb);
        sgemm_kernel<<<dim3(HD / 64, BN / 64), 256>>>(x, Wk, kp,  BN, HD, DIMM, 2, nullptr, nullptr);
        sgemm_kernel<<<dim3(HD / 64, BN / 64), 256>>>(x, Wv, vp,  BN, HD, DIMM, 2, nullptr, nullptr);
    }

    // fused content + relative logits
    logits_kernel<<<dim3(NSEQ / 64, NSEQ / 64, BB * HH), 256, LOGITS_SMEM>>>();

    // softmax
    softmax_kernel<<<BB * HH * NSEQ, 128>>>();

    // attn @ v
    av_kernel<<<dim3(NSEQ / 64, BB * HH), 256>>>();

    // final projection + bias
    {
        float* aop = nullptr; cudaGetSymbolAddress((void**)&aop, g_ao);
        sgemm_kernel<<<dim3(DIMM / 64, BN / 64), 256>>>(aop, Wo, out, BN, DIMM, HD, 3, bo, nullptr);
    }
}

// round 3
// speedup vs baseline: 1.5513x; 1.5513x over previous
#include <cuda_runtime.h>
#include <math.h>

#define BB   2
#define NSEQ 2048
#define DIMM 1536
#define HH   8
#define DKK  64
#define DVV  64
#define NRPF 192
#define NB   32
#define NPOS 4095          // 2N-1
#define BN   4096          // B*N
#define HD   512           // H*DK

typedef unsigned long long ull;

// -------- scratch (device globals; no allocation allowed) --------
__device__ float g_p[NPOS * NB];
__device__ float g_pmax;
__device__ float g_emb[NPOS * NRPF];
__device__ float g_pos[NPOS * HD];
__device__ float g_qc[BB * HH * NSEQ * DKK];
__device__ float g_qp[BB * HH * NSEQ * DKK];
__device__ float g_k [BB * HH * NSEQ * DKK];
__device__ float g_v [BB * HH * NSEQ * DVV];
__device__ float g_logits[(size_t)BB * HH * NSEQ * NSEQ];  // 268 MB
__device__ float g_ao[(size_t)BN * (HH * DVV)];

// ---------------- f32x2 helpers ----------------
__device__ __forceinline__ ull dup2f(float a) {
    ull r; unsigned ai = __float_as_uint(a);
    asm("mov.b64 %0, {%1, %1};" : "=l"(r) : "r"(ai));
    return r;
}
__device__ __forceinline__ ull pack2f(float a, float b) {
    ull r;
    asm("mov.b64 %0, {%1, %2};" : "=l"(r)
        : "r"(__float_as_uint(a)), "r"(__float_as_uint(b)));
    return r;
}
__device__ __forceinline__ void fma2(ull &c, ull a, ull b) {
    asm("fma.rn.f32x2 %0, %1, %2, %0;" : "+l"(c) : "l"(a), "l"(b));
}
__device__ __forceinline__ float2 unpack2f(ull v) {
    unsigned lo, hi;
    asm("mov.b64 {%0, %1}, %2;" : "=r"(lo), "=r"(hi) : "l"(v));
    return make_float2(__uint_as_float(lo), __uint_as_float(hi));
}

// ---------------- positional basis ----------------
__global__ void init_kernel() { g_pmax = 0.0f; }

__global__ void gamma_kernel() {
    int idx = blockIdx.x * blockDim.x + threadIdx.x;
    float p = 0.0f;
    if (idx < NPOS * NB) {
        int row = idx / NB;
        int j   = idx - row * NB;
        double ad   = (double)abs(row - (NSEQ - 1));
        double mean = 64.0 * (double)(j + 1);
        double conc = (mean / 32.0) * (mean / 32.0);
        double rate = mean / 1024.0;
        double xl   = (ad > 0.0) ? (conc - 1.0) * log(ad) : 0.0;
        double logp = xl - rate * ad - (lgamma(conc) - conc * log(rate));
        p = (float)exp(logp) + 1e-8f;
        g_p[idx] = p;
    }
    __shared__ float red[256];
    red[threadIdx.x] = p;
    __syncthreads();
    for (int s = 128; s > 0; s >>= 1) {
        if (threadIdx.x < s) red[threadIdx.x] = fmaxf(red[threadIdx.x], red[threadIdx.x + s]);
        __syncthreads();
    }
    if (threadIdx.x == 0) atomicMax((int*)&g_pmax, __float_as_int(red[0]));
}

__global__ void emb_kernel() {
    int row = blockIdx.x;
    int t   = threadIdx.x;
    int d   = row - (NSEQ - 1);
    float ad = fabsf((float)d);
    float sg = (d > 0) ? 1.0f : ((d < 0) ? -1.0f : 0.0f);
    float f;
    if (t < NB) {
        double maxr = log((double)NSEQ) / log(2.0);
        double xh   = 3.0 + (double)t * (maxr - 3.0) / (double)(NB - 1);
        double hl   = exp2(xh);
        f = (float)exp(-0.6931471805599453 / hl * (double)ad);
    } else if (t < 2 * NB) {
        int jj = t - NB;
        float width = exp2f((float)(jj + 1)) - 1.0f;
        f = (width > ad) ? 1.0f : 0.0f;
    } else {
        f = g_p[row * NB + (t - 2 * NB)] / g_pmax;
    }
    g_emb[row * NRPF + t]      = f;
    g_emb[row * NRPF + 96 + t] = sg * f;
}

// ---------------- generic f32x2 GEMM: 128x128 tile, 8x8 micro ----------------
// C[M,N] = A[M,K] @ B[K,N] (+ bias[N] if bias != nullptr). N%128==0, K%16==0.
__global__ __launch_bounds__(256, 2) void gemm128_kernel(
    const float* __restrict__ A, const float* __restrict__ B, float* __restrict__ C,
    int M, int N, int K, const float* __restrict__ bias)
{
    __shared__ float As[16 * 132];   // [k][m]
    __shared__ float Bs[16 * 132];   // [k][n]
    int tid = threadIdx.x;
    int tx = tid & 15, ty = tid >> 4;
    int j0 = blockIdx.x * 128, i0 = blockIdx.y * 128;
    ull acc[8][4] = {};

    for (int k0 = 0; k0 < K; k0 += 16) {
#pragma unroll
        for (int t = 0; t < 2; t++) {      // A tile 128x16, transposed store
            int idx = tid + t * 256;
            int r = idx >> 2, c4 = (idx & 3) * 4;
            float4 v = make_float4(0.f, 0.f, 0.f, 0.f);
            if (i0 + r < M) v = *(const float4*)&A[(size_t)(i0 + r) * K + k0 + c4];
            As[(c4 + 0) * 132 + r] = v.x; As[(c4 + 1) * 132 + r] = v.y;
            As[(c4 + 2) * 132 + r] = v.z; As[(c4 + 3) * 132 + r] = v.w;
        }
#pragma unroll
        for (int t = 0; t < 2; t++) {      // B tile 16x128
            int idx = tid + t * 256;
            int r = idx >> 5, c4 = (idx & 31) * 4;
            *(float4*)&Bs[r * 132 + c4] = *(const float4*)&B[(size_t)(k0 + r) * N + j0 + c4];
        }
        __syncthreads();
#pragma unroll 4
        for (int kk = 0; kk < 16; kk++) {
            float4 a0 = *(float4*)&As[kk * 132 + ty * 8];
            float4 a1 = *(float4*)&As[kk * 132 + ty * 8 + 4];
            ulonglong2 b0 = *(ulonglong2*)&Bs[kk * 132 + tx * 8];
            ulonglong2 b1 = *(ulonglong2*)&Bs[kk * 132 + tx * 8 + 4];
            ull bp[4] = {b0.x, b0.y, b1.x, b1.y};
            float av[8] = {a0.x, a0.y, a0.z, a0.w, a1.x, a1.y, a1.z, a1.w};
#pragma unroll
            for (int ii = 0; ii < 8; ii++) {
                ull ad = dup2f(av[ii]);
#pragma unroll
                for (int jp = 0; jp < 4; jp++) fma2(acc[ii][jp], ad, bp[jp]);
            }
        }
        __syncthreads();
    }

#pragma unroll
    for (int ii = 0; ii < 8; ii++) {
        int gr = i0 + ty * 8 + ii;
        if (gr >= M) continue;
#pragma unroll
        for (int jp = 0; jp < 4; jp++) {
            int gc = j0 + tx * 8 + 2 * jp;
            float2 v = unpack2f(acc[ii][jp]);
            if (bias) { float2 bv = *(const float2*)&bias[gc]; v.x += bv.x; v.y += bv.y; }
            *(float2*)&C[(size_t)gr * N + gc] = v;
        }
    }
}

// ---------------- fused QKV projection (z = 0/1/2 -> Q/K/V) ----------------
__global__ __launch_bounds__(256, 2) void qkv_kernel(
    const float* __restrict__ x,
    const float* __restrict__ Wq, const float* __restrict__ Wk, const float* __restrict__ Wv,
    const float* __restrict__ cb, const float* __restrict__ pb)
{
    __shared__ float As[16 * 132];
    __shared__ float Bs[16 * 132];
    int z = blockIdx.z;
    const float* W = (z == 0) ? Wq : (z == 1) ? Wk : Wv;
    int tid = threadIdx.x;
    int tx = tid & 15, ty = tid >> 4;
    int j0 = blockIdx.x * 128, i0 = blockIdx.y * 128;
    ull acc[8][4] = {};

    for (int k0 = 0; k0 < DIMM; k0 += 16) {
#pragma unroll
        for (int t = 0; t < 2; t++) {
            int idx = tid + t * 256;
            int r = idx >> 2, c4 = (idx & 3) * 4;
            float4 v = *(const float4*)&x[(size_t)(i0 + r) * DIMM + k0 + c4];
            As[(c4 + 0) * 132 + r] = v.x; As[(c4 + 1) * 132 + r] = v.y;
            As[(c4 + 2) * 132 + r] = v.z; As[(c4 + 3) * 132 + r] = v.w;
        }
#pragma unroll
        for (int t = 0; t < 2; t++) {
            int idx = tid + t * 256;
            int r = idx >> 5, c4 = (idx & 31) * 4;
            *(float4*)&Bs[r * 132 + c4] = *(const float4*)&W[(size_t)(k0 + r) * HD + j0 + c4];
        }
        __syncthreads();
#pragma unroll 4
        for (int kk = 0; kk < 16; kk++) {
            float4 a0 = *(float4*)&As[kk * 132 + ty * 8];
            float4 a1 = *(float4*)&As[kk * 132 + ty * 8 + 4];
            ulonglong2 b0 = *(ulonglong2*)&Bs[kk * 132 + tx * 8];
            ulonglong2 b1 = *(ulonglong2*)&Bs[kk * 132 + tx * 8 + 4];
            ull bp[4] = {b0.x, b0.y, b1.x, b1.y};
            float av[8] = {a0.x, a0.y, a0.z, a0.w, a1.x, a1.y, a1.z, a1.w};
#pragma unroll
            for (int ii = 0; ii < 8; ii++) {
                ull ad = dup2f(av[ii]);
#pragma unroll
                for (int jp = 0; jp < 4; jp++) fma2(acc[ii][jp], ad, bp[jp]);
            }
        }
        __syncthreads();
    }

#pragma unroll
    for (int ii = 0; ii < 8; ii++) {
        int gr = i0 + ty * 8 + ii;
        int b = gr >> 11, n = gr & 2047;
#pragma unroll
        for (int jp = 0; jp < 4; jp++) {
            int gc = j0 + tx * 8 + 2 * jp;
            int h = gc >> 6, dk = gc & 63;
            size_t off = (((size_t)(b * HH + h)) * NSEQ + n) * DKK + dk;
            float2 v = unpack2f(acc[ii][jp]);
            if (z == 0) {
                float q0 = v.x * 0.125f, q1 = v.y * 0.125f;
                float2 cbv = *(const float2*)&cb[gc];
                float2 pbv = *(const float2*)&pb[gc];
                *(float2*)&g_qc[off] = make_float2(q0 + cbv.x, q1 + cbv.y);
                *(float2*)&g_qp[off] = make_float2(q0 + pbv.x, q1 + pbv.y);
            } else if (z == 1) {
                *(float2*)&g_k[off] = v;
            } else {
                *(float2*)&g_v[off] = v;
            }
        }
    }
}

// ---------------- fused logits: content + shifted relative (f32x2) ----------------
// tile 128(i) x 128(j); logits[b,h,i,j] = qc_i.k_j + qp_i.pos[2047+j-i]
__global__ __launch_bounds__(256, 2) void logits_kernel() {
    extern __shared__ float sm[];
    float* qcs  = sm;                        // [128][36]
    float* qps  = sm + 128 * 36;             // [128][36]
    float* ks   = sm + 2 * 128 * 36;         // [32][132]  k-major (transposed)
    float* poss = sm + 2 * 128 * 36 + 32 * 132;  // [32][260] k-major (transposed)

    int bh = blockIdx.z;
    int h  = bh & 7;
    int i0 = blockIdx.y * 128, j0 = blockIdx.x * 128;
    int tid = threadIdx.x;
    int tx = tid & 15, ty = tid >> 4;
    int rbase = (NSEQ - 1) + j0 - i0 - 127;      // 255-row pos band
    int prow0 = 120 + 8 * (tx - ty);             // local pos row for (ii=7,jj=0)

    const float* qcg = g_qc + ((size_t)bh * NSEQ + i0) * DKK;
    const float* qpg = g_qp + ((size_t)bh * NSEQ + i0) * DKK;
    const float* kg  = g_k  + ((size_t)bh * NSEQ + j0) * DKK;
    const float* pg  = g_pos + (size_t)rbase * HD + h * 64;

    ull acc[8][4] = {};

    for (int st = 0; st < 2; st++) {
        int kc = st * 32;
#pragma unroll
        for (int t = 0; t < 4; t++) {            // qc/qp: 128x32
            int idx = tid + t * 256;
            int r = idx >> 3, c4 = (idx & 7) * 4;
            *(float4*)&qcs[r * 36 + c4] = *(const float4*)&qcg[r * 64 + kc + c4];
            *(float4*)&qps[r * 36 + c4] = *(const float4*)&qpg[r * 64 + kc + c4];
        }
#pragma unroll
        for (int t = 0; t < 4; t++) {            // k: 128(j) x 32(k), transposed
            int idx = tid + t * 256;
            int r = idx >> 3, c4 = (idx & 7) * 4;
            float4 v = *(const float4*)&kg[r * 64 + kc + c4];
            ks[(c4 + 0) * 132 + r] = v.x; ks[(c4 + 1) * 132 + r] = v.y;
            ks[(c4 + 2) * 132 + r] = v.z; ks[(c4 + 3) * 132 + r] = v.w;
        }
#pragma unroll
        for (int t = 0; t < 8; t++) {            // pos: 255 x 32, transposed
            int idx = tid + t * 256;
            if (idx < 255 * 8) {
                int r = idx >> 3, c4 = (idx & 7) * 4;
                float4 v = *(const float4*)&pg[(size_t)r * HD + kc + c4];
                poss[(c4 + 0) * 260 + r] = v.x; poss[(c4 + 1) * 260 + r] = v.y;
                poss[(c4 + 2) * 260 + r] = v.z; poss[(c4 + 3) * 260 + r] = v.w;
            }
        }
        __syncthreads();

#pragma unroll 2
        for (int kk = 0; kk < 32; kk++) {
            ull kp[4];
            {
                ulonglong2 t0 = *(ulonglong2*)&ks[kk * 132 + tx * 8];
                ulonglong2 t1 = *(ulonglong2*)&ks[kk * 132 + tx * 8 + 4];
                kp[0] = t0.x; kp[1] = t0.y; kp[2] = t1.x; kp[3] = t1.y;
            }
            float parr[16];
            {
                float4 p0 = *(float4*)&poss[kk * 260 + prow0];
                float4 p1 = *(float4*)&poss[kk * 260 + prow0 + 4];
                float4 p2 = *(float4*)&poss[kk * 260 + prow0 + 8];
                float4 p3 = *(float4*)&poss[kk * 260 + prow0 + 12];
                parr[0] = p0.x; parr[1] = p0.y; parr[2] = p0.z; parr[3] = p0.w;
                parr[4] = p1.x; parr[5] = p1.y; parr[6] = p1.z; parr[7] = p1.w;
                parr[8] = p2.x; parr[9] = p2.y; parr[10] = p2.z; parr[11] = p2.w;
                parr[12] = p3.x; parr[13] = p3.y; parr[14] = p3.z; parr[15] = p3.w;
            }
#pragma unroll
            for (int ii = 0; ii < 8; ii++) {
                int row = ty * 8 + ii;
                ull qcd = dup2f(qcs[row * 36 + kk]);
                ull qpd = dup2f(qps[row * 36 + kk]);
                int tb = 7 - ii;                 // pos pair base for jp=0
                ull pp0 = pack2f(parr[tb],     parr[tb + 1]);
                ull pp1 = pack2f(parr[tb + 2], parr[tb + 3]);
                ull pp2 = pack2f(parr[tb + 4], parr[tb + 5]);
                ull pp3 = pack2f(parr[tb + 6], parr[tb + 7]);
                fma2(acc[ii][0], qcd, kp[0]); fma2(acc[ii][0], qpd, pp0);
                fma2(acc[ii][1], qcd, kp[1]); fma2(acc[ii][1], qpd, pp1);
                fma2(acc[ii][2], qcd, kp[2]); fma2(acc[ii][2], qpd, pp2);
                fma2(acc[ii][3], qcd, kp[3]); fma2(acc[ii][3], qpd, pp3);
            }
        }
        __syncthreads();
    }

    size_t ob = ((size_t)bh * NSEQ + i0 + ty * 8) * NSEQ + j0 + tx * 8;
#pragma unroll
    for (int ii = 0; ii < 8; ii++) {
        ulonglong2 s0, s1;
        s0.x = acc[ii][0]; s0.y = acc[ii][1];
        s1.x = acc[ii][2]; s1.y = acc[ii][3];
        *(ulonglong2*)&g_logits[ob + (size_t)ii * NSEQ]     = s0;
        *(ulonglong2*)&g_logits[ob + (size_t)ii * NSEQ + 4] = s1;
    }
}

// ---------------- softmax over rows of length 2048 ----------------
__global__ __launch_bounds__(128) void softmax_kernel() {
    int row = blockIdx.x;
    float* p = g_logits + (size_t)row * NSEQ;
    int tid = threadIdx.x;
    float4 v[4];
    float m = -1e30f;
#pragma unroll
    for (int e = 0; e < 4; e++) {
        v[e] = *(float4*)&p[tid * 4 + e * 512];
        m = fmaxf(m, fmaxf(fmaxf(v[e].x, v[e].y), fmaxf(v[e].z, v[e].w)));
    }
    __shared__ float red[128];
    red[tid] = m; __syncthreads();
    for (int s = 64; s > 0; s >>= 1) {
        if (tid < s) red[tid] = fmaxf(red[tid], red[tid + s]);
        __syncthreads();
    }
    m = red[0]; __syncthreads();
    float sum = 0.f;
#pragma unroll
    for (int e = 0; e < 4; e++) {
        v[e].x = __expf(v[e].x - m); v[e].y = __expf(v[e].y - m);
        v[e].z = __expf(v[e].z - m); v[e].w = __expf(v[e].w - m);
        sum += v[e].x + v[e].y + v[e].z + v[e].w;
    }
    red[tid] = sum; __syncthreads();
    for (int s = 64; s > 0; s >>= 1) {
        if (tid < s) red[tid] += red[tid + s];
        __syncthreads();
    }
    float inv = 1.0f / red[0];
#pragma unroll
    for (int e = 0; e < 4; e++) {
        v[e].x *= inv; v[e].y *= inv; v[e].z *= inv; v[e].w *= inv;
        *(float4*)&p[tid * 4 + e * 512] = v[e];
    }
}

// ---------------- attn @ v : 128x64 tile, 8x4 micro, f32x2 ----------------
__global__ __launch_bounds__(256, 2) void av_kernel() {
    __shared__ float As[16 * 132];   // [k][i]
    __shared__ float Bs[16 * 68];    // [k][j]
    int bh = blockIdx.y;
    int i0 = blockIdx.x * 128;
    const float* A = g_logits + (size_t)bh * NSEQ * NSEQ;
    const float* V = g_v + (size_t)bh * NSEQ * DVV;
    int tid = threadIdx.x;
    int tx = tid & 15, ty = tid >> 4;
    ull acc[8][2] = {};

    for (int k0 = 0; k0 < NSEQ; k0 += 16) {
#pragma unroll
        for (int t = 0; t < 2; t++) {          // A tile 128x16, transposed
            int idx = tid + t * 256;
            int r = idx >> 2, c4 = (idx & 3) * 4;
            float4 v = *(const float4*)&A[(size_t)(i0 + r) * NSEQ + k0 + c4];
            As[(c4 + 0) * 132 + r] = v.x; As[(c4 + 1) * 132 + r] = v.y;
            As[(c4 + 2) * 132 + r] = v.z; As[(c4 + 3) * 132 + r] = v.w;
        }
        {                                       // B tile 16x64
            int r = tid >> 4, c4 = (tid & 15) * 4;
            *(float4*)&Bs[r * 68 + c4] = *(const float4*)&V[(size_t)(k0 + r) * DVV + c4];
        }
        __syncthreads();
#pragma unroll 4
        for (int kk = 0; kk < 16; kk++) {
            float4 a0 = *(float4*)&As[kk * 132 + ty * 8];
            float4 a1 = *(float4*)&As[kk * 132 + ty * 8 + 4];
            ulonglong2 b0 = *(ulonglong2*)&Bs[kk * 68 + tx * 4];
            ull bp[2] = {b0.x, b0.y};
            float av[8] = {a0.x, a0.y, a0.z, a0.w, a1.x, a1.y, a1.z, a1.w};
#pragma unroll
            for (int ii = 0; ii < 8; ii++) {
                ull ad = dup2f(av[ii]);
                fma2(acc[ii][0], ad, bp[0]);
                fma2(acc[ii][1], ad, bp[1]);
            }
        }
        __syncthreads();
    }

    int b = bh >> 3, hh = bh & 7;
#pragma unroll
    for (int ii = 0; ii < 8; ii++) {
        int n = i0 + ty * 8 + ii;
        ulonglong2 s; s.x = acc[ii][0]; s.y = acc[ii][1];
        *(ulonglong2*)&g_ao[((size_t)(b * NSEQ + n)) * HD + hh * 64 + tx * 4] = s;
    }
}

// ---------------- launch ----------------
extern "C" void kernel_launch(void* const* d_in, const int* in_sizes, int n_in,
                              void* d_out, int out_size) {
    const float* x    = (const float*)d_in[0];
    const float* Wq   = (const float*)d_in[1];
    const float* Wk   = (const float*)d_in[2];
    const float* Wv   = (const float*)d_in[3];
    const float* Wo   = (const float*)d_in[4];
    const float* bo   = (const float*)d_in[5];
    const float* Wrel = (const float*)d_in[6];
    const float* cb   = (const float*)d_in[7];
    const float* pb   = (const float*)d_in[8];
    float* out = (float*)d_out;

    const int LOGITS_SMEM = (2 * 128 * 36 + 32 * 132 + 32 * 260) * 4;  // 87040 B
    cudaFuncSetAttribute(logits_kernel, cudaFuncAttributeMaxDynamicSharedMemorySize, LOGITS_SMEM);

    // positional basis
    init_kernel<<<1, 1>>>();
    gamma_kernel<<<(NPOS * NB + 255) / 256, 256>>>();
    emb_kernel<<<NPOS, 96>>>();

    // pos = emb @ Wrel   [4095 x 512]
    {
        float* posp = nullptr; cudaGetSymbolAddress((void**)&posp, g_pos);
        float* embp = nullptr; cudaGetSymbolAddress((void**)&embp, g_emb);
        gemm128_kernel<<<dim3(HD / 128, (NPOS + 127) / 128), 256>>>(
            embp, Wrel, posp, NPOS, HD, NRPF, nullptr);
    }

    // fused Q/K/V projections
    qkv_kernel<<<dim3(HD / 128, BN / 128, 3), 256>>>(x, Wq, Wk, Wv, cb, pb);

    // fused content + relative logits
    logits_kernel<<<dim3(NSEQ / 128, NSEQ / 128, BB * HH), 256, LOGITS_SMEM>>>();

    // softmax
    softmax_kernel<<<BB * HH * NSEQ, 128>>>();

    // attn @ v
    av_kernel<<<dim3(NSEQ / 128, BB * HH), 256>>>();

    // final projection + bias
    {
        float* aop = nullptr; cudaGetSymbolAddress((void**)&aop, g_ao);
        gemm128_kernel<<<dim3(DIMM / 128, BN / 128), 256>>>(aop, Wo, out, BN, DIMM, HD, bo);
    }
}

// round 7
// speedup vs baseline: 2.0423x; 1.3165x over previous
#include <cuda_runtime.h>
#include <cuda_bf16.h>
#include <mma.h>
#include <cstdint>
#include <math.h>

using namespace nvcuda;

#define BB   2
#define NSEQ 2048
#define DIMM 1536
#define HH   8
#define DKK  64
#define DVV  64
#define NRPF 192
#define NB   32
#define NPOS 4095          // 2N-1
#define BN   4096          // B*N
#define HD   512           // H*DK

typedef unsigned long long ull;

// -------- scratch (device globals; no allocation allowed) --------
__device__ float g_p[NPOS * NB];
__device__ float g_pmax;
__device__ float g_emb[NPOS * NRPF];
__device__ float g_pos[NPOS * HD];
__device__ float g_qc[BB * HH * NSEQ * DKK];
__device__ float g_qp[BB * HH * NSEQ * DKK];
__device__ float g_k [BB * HH * NSEQ * DKK];
__device__ float g_logits[(size_t)BB * HH * NSEQ * NSEQ];      // 268 MB
// bf16 split operands
__device__ __nv_bfloat16 g_xh[(size_t)BN * DIMM];
__device__ __nv_bfloat16 g_xl[(size_t)BN * DIMM];
__device__ __nv_bfloat16 g_wth[(size_t)3 * HD * DIMM];          // Wq/Wk/Wv transposed [z][512][1536]
__device__ __nv_bfloat16 g_wtl[(size_t)3 * HD * DIMM];
__device__ __nv_bfloat16 g_woth[(size_t)DIMM * HD];             // Wo^T [1536][512]
__device__ __nv_bfloat16 g_wotl[(size_t)DIMM * HD];
__device__ __nv_bfloat16 g_vth[(size_t)BB * HH * DVV * NSEQ];   // v^T per bh: [16][64][2048]
__device__ __nv_bfloat16 g_vtl[(size_t)BB * HH * DVV * NSEQ];
__device__ __nv_bfloat16 g_ph[(size_t)BB * HH * NSEQ * NSEQ];   // probs split
__device__ __nv_bfloat16 g_pl[(size_t)BB * HH * NSEQ * NSEQ];
__device__ __nv_bfloat16 g_aoh[(size_t)BN * HD];
__device__ __nv_bfloat16 g_aol[(size_t)BN * HD];

// ---------------- f32x2 helpers (logits / pos kernels) ----------------
__device__ __forceinline__ ull dup2f(float a) {
    ull r; unsigned ai = __float_as_uint(a);
    asm("mov.b64 %0, {%1, %1};" : "=l"(r) : "r"(ai));
    return r;
}
__device__ __forceinline__ ull pack2f(float a, float b) {
    ull r;
    asm("mov.b64 %0, {%1, %2};" : "=l"(r)
        : "r"(__float_as_uint(a)), "r"(__float_as_uint(b)));
    return r;
}
__device__ __forceinline__ void fma2(ull &c, ull a, ull b) {
    asm("fma.rn.f32x2 %0, %1, %2, %0;" : "+l"(c) : "l"(a), "l"(b));
}

__device__ __forceinline__ void split2(float f, __nv_bfloat16 &h, __nv_bfloat16 &l) {
    h = __float2bfloat16(f);
    l = __float2bfloat16(f - __bfloat162float(h));
}

// ---------------- positional basis ----------------
__global__ void init_kernel() { g_pmax = 0.0f; }

__global__ void gamma_kernel() {
    int idx = blockIdx.x * blockDim.x + threadIdx.x;
    float p = 0.0f;
    if (idx < NPOS * NB) {
        int row = idx / NB;
        int j   = idx - row * NB;
        double ad   = (double)abs(row - (NSEQ - 1));
        double mean = 64.0 * (double)(j + 1);
        double conc = (mean / 32.0) * (mean / 32.0);
        double rate = mean / 1024.0;
        double xl   = (ad > 0.0) ? (conc - 1.0) * log(ad) : 0.0;
        double logp = xl - rate * ad - (lgamma(conc) - conc * log(rate));
        p = (float)exp(logp) + 1e-8f;
        g_p[idx] = p;
    }
    __shared__ float red[256];
    red[threadIdx.x] = p;
    __syncthreads();
    for (int s = 128; s > 0; s >>= 1) {
        if (threadIdx.x < s) red[threadIdx.x] = fmaxf(red[threadIdx.x], red[threadIdx.x + s]);
        __syncthreads();
    }
    if (threadIdx.x == 0) atomicMax((int*)&g_pmax, __float_as_int(red[0]));
}

__global__ void emb_kernel() {
    int row = blockIdx.x;
    int t   = threadIdx.x;
    int d   = row - (NSEQ - 1);
    float ad = fabsf((float)d);
    float sg = (d > 0) ? 1.0f : ((d < 0) ? -1.0f : 0.0f);
    float f;
    if (t < NB) {
        double maxr = log((double)NSEQ) / log(2.0);
        double xh   = 3.0 + (double)t * (maxr - 3.0) / (double)(NB - 1);
        double hl   = exp2(xh);
        f = (float)exp(-0.6931471805599453 / hl * (double)ad);
    } else if (t < 2 * NB) {
        int jj = t - NB;
        float width = exp2f((float)(jj + 1)) - 1.0f;
        f = (width > ad) ? 1.0f : 0.0f;
    } else {
        f = g_p[row * NB + (t - 2 * NB)] / g_pmax;
    }
    g_emb[row * NRPF + t]      = f;
    g_emb[row * NRPF + 96 + t] = sg * f;
}

// ---------------- f32x2 GEMM (pos projection only) ----------------
__global__ __launch_bounds__(256, 2) void gemm128_kernel(
    const float* __restrict__ A, const float* __restrict__ B, float* __restrict__ C,
    int M, int N, int K)
{
    __shared__ float As[16 * 132];
    __shared__ float Bs[16 * 132];
    int tid = threadIdx.x;
    int tx = tid & 15, ty = tid >> 4;
    int j0 = blockIdx.x * 128, i0 = blockIdx.y * 128;
    ull acc[8][4] = {};
    for (int k0 = 0; k0 < K; k0 += 16) {
#pragma unroll
        for (int t = 0; t < 2; t++) {
            int idx = tid + t * 256;
            int r = idx >> 2, c4 = (idx & 3) * 4;
            float4 v = make_float4(0.f, 0.f, 0.f, 0.f);
            if (i0 + r < M) v = *(const float4*)&A[(size_t)(i0 + r) * K + k0 + c4];
            As[(c4 + 0) * 132 + r] = v.x; As[(c4 + 1) * 132 + r] = v.y;
            As[(c4 + 2) * 132 + r] = v.z; As[(c4 + 3) * 132 + r] = v.w;
        }
#pragma unroll
        for (int t = 0; t < 2; t++) {
            int idx = tid + t * 256;
            int r = idx >> 5, c4 = (idx & 31) * 4;
            *(float4*)&Bs[r * 132 + c4] = *(const float4*)&B[(size_t)(k0 + r) * N + j0 + c4];
        }
        __syncthreads();
#pragma unroll 4
        for (int kk = 0; kk < 16; kk++) {
            float4 a0 = *(float4*)&As[kk * 132 + ty * 8];
            float4 a1 = *(float4*)&As[kk * 132 + ty * 8 + 4];
            ulonglong2 b0 = *(ulonglong2*)&Bs[kk * 132 + tx * 8];
            ulonglong2 b1 = *(ulonglong2*)&Bs[kk * 132 + tx * 8 + 4];
            ull bp[4] = {b0.x, b0.y, b1.x, b1.y};
            float av[8] = {a0.x, a0.y, a0.z, a0.w, a1.x, a1.y, a1.z, a1.w};
#pragma unroll
            for (int ii = 0; ii < 8; ii++) {
                ull ad = dup2f(av[ii]);
#pragma unroll
                for (int jp = 0; jp < 4; jp++) fma2(acc[ii][jp], ad, bp[jp]);
            }
        }
        __syncthreads();
    }
#pragma unroll
    for (int ii = 0; ii < 8; ii++) {
        int gr = i0 + ty * 8 + ii;
        if (gr >= M) continue;
#pragma unroll
        for (int jp = 0; jp < 4; jp++) {
            int gc = j0 + tx * 8 + 2 * jp;
            ull v = acc[ii][jp];
            unsigned lo, hi;
            asm("mov.b64 {%0, %1}, %2;" : "=r"(lo), "=r"(hi) : "l"(v));
            *(float2*)&C[(size_t)gr * N + gc] =
                make_float2(__uint_as_float(lo), __uint_as_float(hi));
        }
    }
}

// ---------------- prep: split x into bf16 hi/lo ----------------
__global__ void split_x_kernel(const float* __restrict__ x) {
    size_t i = ((size_t)blockIdx.x * 256 + threadIdx.x) * 4;
    float4 v = *(const float4*)(x + i);
    __nv_bfloat16 h0, l0, h1, l1, h2, l2, h3, l3;
    split2(v.x, h0, l0); split2(v.y, h1, l1);
    split2(v.z, h2, l2); split2(v.w, h3, l3);
    *(__nv_bfloat162*)(g_xh + i)     = __halves2bfloat162(h0, h1);
    *(__nv_bfloat162*)(g_xh + i + 2) = __halves2bfloat162(h2, h3);
    *(__nv_bfloat162*)(g_xl + i)     = __halves2bfloat162(l0, l1);
    *(__nv_bfloat162*)(g_xl + i + 2) = __halves2bfloat162(l2, l3);
}

// ---------------- prep: transpose + split weight [K,N] -> [N,K] ----------------
__global__ void wtrans_kernel(const float* __restrict__ src,
                              __nv_bfloat16* __restrict__ dh, __nv_bfloat16* __restrict__ dl,
                              int K, int N) {
    __shared__ float t[32][33];
    int n0 = blockIdx.x * 32, k0 = blockIdx.y * 32;
    int tx = threadIdx.x, ty = threadIdx.y;   // 32 x 8
#pragma unroll
    for (int r = 0; r < 4; r++)
        t[ty + r * 8][tx] = src[(size_t)(k0 + ty + r * 8) * N + n0 + tx];
    __syncthreads();
#pragma unroll
    for (int r = 0; r < 4; r++) {
        int n = n0 + ty + r * 8;
        float v = t[tx][ty + r * 8];
        __nv_bfloat16 h, l; split2(v, h, l);
        dh[(size_t)n * K + k0 + tx] = h;
        dl[(size_t)n * K + k0 + tx] = l;
    }
}

// ================= wmma GEMM kernels (bf16x3 split, fp32 accum) ==========
// layout per CTA: 256 thr = 8 warps.
// qkv/proj: warp grid 4x2, warp tile 32x64 -> acc[2][4]; CTA 128x128.
// smem: staging (Ah,Al,Bh,Bl 128x48 bf16 = 49152B) overlaid with C_s (128x132 f32 = 67584B)
#define GSTAGE_LD 48
#define GEMM_SMEM 67584

typedef wmma::fragment<wmma::matrix_a, 16, 16, 16, __nv_bfloat16, wmma::row_major> FragA;
typedef wmma::fragment<wmma::matrix_b, 16, 16, 16, __nv_bfloat16, wmma::col_major> FragB;
typedef wmma::fragment<wmma::accumulator, 16, 16, 16, float> FragC;

// generic 128x128xK mainloop: returns with C_s (f32, ldm 132) filled
__device__ __forceinline__ void wmma_main_128x128(
    char* sm, int tid,
    const __nv_bfloat16* Ah_g, const __nv_bfloat16* Al_g,   // rows i0.., stride K
    const __nv_bfloat16* Bh_g, const __nv_bfloat16* Bl_g,   // rows j0.., stride K
    int K)
{
    __nv_bfloat16* Ah_s = (__nv_bfloat16*)sm;
    __nv_bfloat16* Al_s = Ah_s + 128 * GSTAGE_LD;
    __nv_bfloat16* Bh_s = Al_s + 128 * GSTAGE_LD;
    __nv_bfloat16* Bl_s = Bh_s + 128 * GSTAGE_LD;
    int wid = tid >> 5;
    int wrow = wid >> 1, wcol = wid & 1;

    FragC acc[2][4];
#pragma unroll
    for (int m = 0; m < 2; m++)
#pragma unroll
        for (int n = 0; n < 4; n++) wmma::fill_fragment(acc[m][n], 0.0f);

    for (int kc = 0; kc < K; kc += 32) {
        __syncthreads();
#pragma unroll
        for (int t = 0; t < 2; t++) {
            int idx = tid + t * 256;
            int r = idx >> 2, c8 = (idx & 3) * 8;
            *(uint4*)&Ah_s[r * GSTAGE_LD + c8] = *(const uint4*)&Ah_g[(size_t)r * K + kc + c8];
            *(uint4*)&Al_s[r * GSTAGE_LD + c8] = *(const uint4*)&Al_g[(size_t)r * K + kc + c8];
            *(uint4*)&Bh_s[r * GSTAGE_LD + c8] = *(const uint4*)&Bh_g[(size_t)r * K + kc + c8];
            *(uint4*)&Bl_s[r * GSTAGE_LD + c8] = *(const uint4*)&Bl_g[(size_t)r * K + kc + c8];
        }
        __syncthreads();
#pragma unroll
        for (int kk = 0; kk < 32; kk += 16) {
            FragA fah[2], fal[2];
            FragB fbh[4], fbl[4];
#pragma unroll
            for (int m = 0; m < 2; m++) {
                wmma::load_matrix_sync(fah[m], Ah_s + (wrow * 32 + m * 16) * GSTAGE_LD + kk, GSTAGE_LD);
                wmma::load_matrix_sync(fal[m], Al_s + (wrow * 32 + m * 16) * GSTAGE_LD + kk, GSTAGE_LD);
            }
#pragma unroll
            for (int n = 0; n < 4; n++) {
                wmma::load_matrix_sync(fbh[n], Bh_s + (wcol * 64 + n * 16) * GSTAGE_LD + kk, GSTAGE_LD);
                wmma::load_matrix_sync(fbl[n], Bl_s + (wcol * 64 + n * 16) * GSTAGE_LD + kk, GSTAGE_LD);
            }
#pragma unroll
            for (int m = 0; m < 2; m++)
#pragma unroll
                for (int n = 0; n < 4; n++) {
                    wmma::mma_sync(acc[m][n], fah[m], fbh[n], acc[m][n]);
                    wmma::mma_sync(acc[m][n], fah[m], fbl[n], acc[m][n]);
                    wmma::mma_sync(acc[m][n], fal[m], fbh[n], acc[m][n]);
                }
        }
    }
    __syncthreads();
    float* C_s = (float*)sm;
#pragma unroll
    for (int m = 0; m < 2; m++)
#pragma unroll
        for (int n = 0; n < 4; n++)
            wmma::store_matrix_sync(C_s + (wrow * 32 + m * 16) * 132 + wcol * 64 + n * 16,
                                    acc[m][n], 132, wmma::mem_row_major);
    __syncthreads();
}

// ---- QKV: M=128 (bn), N=128 (hd), K=1536. z: 0=Q, 1=K, 2=V ----
__global__ __launch_bounds__(256, 2) void qkv_wmma_kernel(
    const float* __restrict__ cb, const float* __restrict__ pb)
{
    extern __shared__ char sm[];
    int tid = threadIdx.x;
    int z = blockIdx.z;
    int i0 = blockIdx.y * 128, j0 = blockIdx.x * 128;
    wmma_main_128x128(sm, tid,
        g_xh + (size_t)i0 * DIMM, g_xl + (size_t)i0 * DIMM,
        g_wth + (size_t)z * HD * DIMM + (size_t)j0 * DIMM,
        g_wtl + (size_t)z * HD * DIMM + (size_t)j0 * DIMM, DIMM);
    float* C_s = (float*)sm;

    if (z == 0) {
        for (int e = tid; e < 128 * 128; e += 256) {
            int r = e >> 7, c = e & 127;
            float val = C_s[r * 132 + c];
            int gr = i0 + r, gc = j0 + c;
            int b = gr >> 11, n = gr & 2047;
            int h = gc >> 6, dk = gc & 63;
            size_t off = (((size_t)(b * HH + h)) * NSEQ + n) * DKK + dk;
            float q = val * 0.125f;
            g_qc[off] = q + cb[gc];
            g_qp[off] = q + pb[gc];
        }
    } else if (z == 1) {
        for (int e = tid; e < 128 * 128; e += 256) {
            int r = e >> 7, c = e & 127;
            int gr = i0 + r, gc = j0 + c;
            int b = gr >> 11, n = gr & 2047;
            int h = gc >> 6, dk = gc & 63;
            g_k[(((size_t)(b * HH + h)) * NSEQ + n) * DKK + dk] = C_s[r * 132 + c];
        }
    } else {
        for (int e = tid; e < 128 * 128; e += 256) {
            int r = e & 127, c = e >> 7;        // column-major walk: coalesced on n
            float val = C_s[r * 132 + c];
            int gr = i0 + r, gc = j0 + c;
            int b = gr >> 11, n = gr & 2047;
            int h = gc >> 6, dk = gc & 63;
            __nv_bfloat16 hh_, ll_;
            split2(val, hh_, ll_);
            size_t off = (((size_t)(b * HH + h)) * DVV + dk) * NSEQ + n;
            g_vth[off] = hh_; g_vtl[off] = ll_;
        }
    }
}

// ---- final projection: M=128 (bn), N=128 (dim), K=512 ----
__global__ __launch_bounds__(256, 2) void proj_wmma_kernel(
    float* __restrict__ out, const float* __restrict__ bo)
{
    extern __shared__ char sm[];
    int tid = threadIdx.x;
    int i0 = blockIdx.y * 128, j0 = blockIdx.x * 128;
    wmma_main_128x128(sm, tid,
        g_aoh + (size_t)i0 * HD, g_aol + (size_t)i0 * HD,
        g_woth + (size_t)j0 * HD, g_wotl + (size_t)j0 * HD, HD);
    float* C_s = (float*)sm;
    for (int e = tid; e < 128 * 128; e += 256) {
        int r = e >> 7, c = e & 127;
        out[(size_t)(i0 + r) * DIMM + j0 + c] = C_s[r * 132 + c] + bo[j0 + c];
    }
}

// ---- attn@V: per bh, M=128 (i), N=64 (d), K=2048 ----
// 8 warps, warp tile 16x64 -> acc[4]. smem: staging 36864B overlaid C_s 128x68 f32.
#define AV_SMEM 36864
__global__ __launch_bounds__(256, 2) void av_wmma_kernel()
{
    extern __shared__ char sm[];
    int tid = threadIdx.x, wid = tid >> 5;
    int bh = blockIdx.y;
    int i0 = blockIdx.x * 128;
    const __nv_bfloat16* Ah_g = g_ph + (size_t)bh * NSEQ * NSEQ + (size_t)i0 * NSEQ;
    const __nv_bfloat16* Al_g = g_pl + (size_t)bh * NSEQ * NSEQ + (size_t)i0 * NSEQ;
    const __nv_bfloat16* Bh_g = g_vth + (size_t)bh * DVV * NSEQ;
    const __nv_bfloat16* Bl_g = g_vtl + (size_t)bh * DVV * NSEQ;

    __nv_bfloat16* Ah_s = (__nv_bfloat16*)sm;
    __nv_bfloat16* Al_s = Ah_s + 128 * GSTAGE_LD;
    __nv_bfloat16* Bh_s = Al_s + 128 * GSTAGE_LD;
    __nv_bfloat16* Bl_s = Bh_s + 64 * GSTAGE_LD;

    FragC acc[4];
#pragma unroll
    for (int n = 0; n < 4; n++) wmma::fill_fragment(acc[n], 0.0f);

    for (int kc = 0; kc < NSEQ; kc += 32) {
        __syncthreads();
#pragma unroll
        for (int t = 0; t < 2; t++) {
            int idx = tid + t * 256;
            int r = idx >> 2, c8 = (idx & 3) * 8;
            *(uint4*)&Ah_s[r * GSTAGE_LD + c8] = *(const uint4*)&Ah_g[(size_t)r * NSEQ + kc + c8];
            *(uint4*)&Al_s[r * GSTAGE_LD + c8] = *(const uint4*)&Al_g[(size_t)r * NSEQ + kc + c8];
        }
        {
            int r = tid >> 2, c8 = (tid & 3) * 8;
            if (r < 64) {
                *(uint4*)&Bh_s[r * GSTAGE_LD + c8] = *(const uint4*)&Bh_g[(size_t)r * NSEQ + kc + c8];
                *(uint4*)&Bl_s[r * GSTAGE_LD + c8] = *(const uint4*)&Bl_g[(size_t)r * NSEQ + kc + c8];
            }
        }
        __syncthreads();
#pragma unroll
        for (int kk = 0; kk < 32; kk += 16) {
            FragA fah, fal;
            FragB fbh[4], fbl[4];
            wmma::load_matrix_sync(fah, Ah_s + (wid * 16) * GSTAGE_LD + kk, GSTAGE_LD);
            wmma::load_matrix_sync(fal, Al_s + (wid * 16) * GSTAGE_LD + kk, GSTAGE_LD);
#pragma unroll
            for (int n = 0; n < 4; n++) {
                wmma::load_matrix_sync(fbh[n], Bh_s + (n * 16) * GSTAGE_LD + kk, GSTAGE_LD);
                wmma::load_matrix_sync(fbl[n], Bl_s + (n * 16) * GSTAGE_LD + kk, GSTAGE_LD);
            }
#pragma unroll
            for (int n = 0; n < 4; n++) {
                wmma::mma_sync(acc[n], fah, fbh[n], acc[n]);
                wmma::mma_sync(acc[n], fah, fbl[n], acc[n]);
                wmma::mma_sync(acc[n], fal, fbh[n], acc[n]);
            }
        }
    }
    __syncthreads();
    float* C_s = (float*)sm;   // 128 x 68
#pragma unroll
    for (int n = 0; n < 4; n++)
        wmma::store_matrix_sync(C_s + (wid * 16) * 68 + n * 16, acc[n], 68, wmma::mem_row_major);
    __syncthreads();

    int b = bh >> 3, h = bh & 7;
    for (int e = tid; e < 128 * 64; e += 256) {
        int r = e >> 6, c = e & 63;
        float val = C_s[r * 68 + c];
        int n = i0 + r;
        __nv_bfloat16 hh_, ll_;
        split2(val, hh_, ll_);
        size_t off = ((size_t)(b * NSEQ + n)) * HD + h * 64 + c;
        g_aoh[off] = hh_; g_aol[off] = ll_;
    }
}

// ---------------- fused logits (f32x2, known-good) ----------------
__global__ __launch_bounds__(256, 2) void logits_kernel() {
    extern __shared__ float smf[];
    float* qcs  = smf;
    float* qps  = smf + 128 * 36;
    float* ks   = smf + 2 * 128 * 36;
    float* poss = smf + 2 * 128 * 36 + 32 * 132;

    int bh = blockIdx.z;
    int h  = bh & 7;
    int i0 = blockIdx.y * 128, j0 = blockIdx.x * 128;
    int tid = threadIdx.x;
    int tx = tid & 15, ty = tid >> 4;
    int rbase = (NSEQ - 1) + j0 - i0 - 127;
    int prow0 = 120 + 8 * (tx - ty);

    const float* qcg = g_qc + ((size_t)bh * NSEQ + i0) * DKK;
    const float* qpg = g_qp + ((size_t)bh * NSEQ + i0) * DKK;
    const float* kg  = g_k  + ((size_t)bh * NSEQ + j0) * DKK;
    const float* pg  = g_pos + (size_t)rbase * HD + h * 64;

    ull acc[8][4] = {};
    for (int st = 0; st < 2; st++) {
        int kc = st * 32;
#pragma unroll
        for (int t = 0; t < 4; t++) {
            int idx = tid + t * 256;
            int r = idx >> 3, c4 = (idx & 7) * 4;
            *(float4*)&qcs[r * 36 + c4] = *(const float4*)&qcg[r * 64 + kc + c4];
            *(float4*)&qps[r * 36 + c4] = *(const float4*)&qpg[r * 64 + kc + c4];
        }
#pragma unroll
        for (int t = 0; t < 4; t++) {
            int idx = tid + t * 256;
            int r = idx >> 3, c4 = (idx & 7) * 4;
            float4 v = *(const float4*)&kg[r * 64 + kc + c4];
            ks[(c4 + 0) * 132 + r] = v.x; ks[(c4 + 1) * 132 + r] = v.y;
            ks[(c4 + 2) * 132 + r] = v.z; ks[(c4 + 3) * 132 + r] = v.w;
        }
#pragma unroll
        for (int t = 0; t < 8; t++) {
            int idx = tid + t * 256;
            if (idx < 255 * 8) {
                int r = idx >> 3, c4 = (idx & 7) * 4;
                float4 v = *(const float4*)&pg[(size_t)r * HD + kc + c4];
                poss[(c4 + 0) * 260 + r] = v.x; poss[(c4 + 1) * 260 + r] = v.y;
                poss[(c4 + 2) * 260 + r] = v.z; poss[(c4 + 3) * 260 + r] = v.w;
            }
        }
        __syncthreads();
#pragma unroll 2
        for (int kk = 0; kk < 32; kk++) {
            ull kp[4];
            {
                ulonglong2 t0 = *(ulonglong2*)&ks[kk * 132 + tx * 8];
                ulonglong2 t1 = *(ulonglong2*)&ks[kk * 132 + tx * 8 + 4];
                kp[0] = t0.x; kp[1] = t0.y; kp[2] = t1.x; kp[3] = t1.y;
            }
            float parr[16];
            {
                float4 p0 = *(float4*)&poss[kk * 260 + prow0];
                float4 p1 = *(float4*)&poss[kk * 260 + prow0 + 4];
                float4 p2 = *(float4*)&poss[kk * 260 + prow0 + 8];
                float4 p3 = *(float4*)&poss[kk * 260 + prow0 + 12];
                parr[0] = p0.x; parr[1] = p0.y; parr[2] = p0.z; parr[3] = p0.w;
                parr[4] = p1.x; parr[5] = p1.y; parr[6] = p1.z; parr[7] = p1.w;
                parr[8] = p2.x; parr[9] = p2.y; parr[10] = p2.z; parr[11] = p2.w;
                parr[12] = p3.x; parr[13] = p3.y; parr[14] = p3.z; parr[15] = p3.w;
            }
#pragma unroll
            for (int ii = 0; ii < 8; ii++) {
                int row = ty * 8 + ii;
                ull qcd = dup2f(qcs[row * 36 + kk]);
                ull qpd = dup2f(qps[row * 36 + kk]);
                int tbx = 7 - ii;
                ull pp0 = pack2f(parr[tbx],     parr[tbx + 1]);
                ull pp1 = pack2f(parr[tbx + 2], parr[tbx + 3]);
                ull pp2 = pack2f(parr[tbx + 4], parr[tbx + 5]);
                ull pp3 = pack2f(parr[tbx + 6], parr[tbx + 7]);
                fma2(acc[ii][0], qcd, kp[0]); fma2(acc[ii][0], qpd, pp0);
                fma2(acc[ii][1], qcd, kp[1]); fma2(acc[ii][1], qpd, pp1);
                fma2(acc[ii][2], qcd, kp[2]); fma2(acc[ii][2], qpd, pp2);
                fma2(acc[ii][3], qcd, kp[3]); fma2(acc[ii][3], qpd, pp3);
            }
        }
        __syncthreads();
    }
    size_t ob = ((size_t)bh * NSEQ + i0 + ty * 8) * NSEQ + j0 + tx * 8;
#pragma unroll
    for (int ii = 0; ii < 8; ii++) {
        ulonglong2 s0, s1;
        s0.x = acc[ii][0]; s0.y = acc[ii][1];
        s1.x = acc[ii][2]; s1.y = acc[ii][3];
        *(ulonglong2*)&g_logits[ob + (size_t)ii * NSEQ]     = s0;
        *(ulonglong2*)&g_logits[ob + (size_t)ii * NSEQ + 4] = s1;
    }
}

// ---------------- softmax -> bf16 hi/lo probs ----------------
__global__ __launch_bounds__(128) void softmax_kernel() {
    size_t row = blockIdx.x;
    const float* p = g_logits + row * NSEQ;
    int tid = threadIdx.x;
    float4 v[4];
    float m = -1e30f;
#pragma unroll
    for (int e = 0; e < 4; e++) {
        v[e] = *(const float4*)&p[tid * 4 + e * 512];
        m = fmaxf(m, fmaxf(fmaxf(v[e].x, v[e].y), fmaxf(v[e].z, v[e].w)));
    }
    __shared__ float red[128];
    red[tid] = m; __syncthreads();
    for (int s = 64; s > 0; s >>= 1) {
        if (tid < s) red[tid] = fmaxf(red[tid], red[tid + s]);
        __syncthreads();
    }
    m = red[0]; __syncthreads();
    float sum = 0.f;
#pragma unroll
    for (int e = 0; e < 4; e++) {
        v[e].x = __expf(v[e].x - m); v[e].y = __expf(v[e].y - m);
        v[e].z = __expf(v[e].z - m); v[e].w = __expf(v[e].w - m);
        sum += v[e].x + v[e].y + v[e].z + v[e].w;
    }
    red[tid] = sum; __syncthreads();
    for (int s = 64; s > 0; s >>= 1) {
        if (tid < s) red[tid] += red[tid + s];
        __syncthreads();
    }
    float inv = 1.0f / red[0];
    __nv_bfloat16* ph = g_ph + row * NSEQ;
    __nv_bfloat16* pl = g_pl + row * NSEQ;
#pragma unroll
    for (int e = 0; e < 4; e++) {
        float p0 = v[e].x * inv, p1 = v[e].y * inv, p2 = v[e].z * inv, p3 = v[e].w * inv;
        __nv_bfloat16 h0, l0, h1, l1, h2, l2, h3, l3;
        split2(p0, h0, l0); split2(p1, h1, l1); split2(p2, h2, l2); split2(p3, h3, l3);
        int base = tid * 4 + e * 512;
        *(__nv_bfloat162*)&ph[base]     = __halves2bfloat162(h0, h1);
        *(__nv_bfloat162*)&ph[base + 2] = __halves2bfloat162(h2, h3);
        *(__nv_bfloat162*)&pl[base]     = __halves2bfloat162(l0, l1);
        *(__nv_bfloat162*)&pl[base + 2] = __halves2bfloat162(l2, l3);
    }
}

// ---------------- launch ----------------
extern "C" void kernel_launch(void* const* d_in, const int* in_sizes, int n_in,
                              void* d_out, int out_size) {
    const float* x    = (const float*)d_in[0];
    const float* Wq   = (const float*)d_in[1];
    const float* Wk   = (const float*)d_in[2];
    const float* Wv   = (const float*)d_in[3];
    const float* Wo   = (const float*)d_in[4];
    const float* bo   = (const float*)d_in[5];
    const float* Wrel = (const float*)d_in[6];
    const float* cb   = (const float*)d_in[7];
    const float* pb   = (const float*)d_in[8];
    float* out = (float*)d_out;

    const int LOGITS_SMEM = (2 * 128 * 36 + 32 * 132 + 32 * 260) * 4;  // 87040
    cudaFuncSetAttribute(logits_kernel, cudaFuncAttributeMaxDynamicSharedMemorySize, LOGITS_SMEM);
    cudaFuncSetAttribute(qkv_wmma_kernel, cudaFuncAttributeMaxDynamicSharedMemorySize, GEMM_SMEM);
    cudaFuncSetAttribute(proj_wmma_kernel, cudaFuncAttributeMaxDynamicSharedMemorySize, GEMM_SMEM);
    cudaFuncSetAttribute(av_wmma_kernel, cudaFuncAttributeMaxDynamicSharedMemorySize, AV_SMEM);

    // positional basis
    init_kernel<<<1, 1>>>();
    gamma_kernel<<<(NPOS * NB + 255) / 256, 256>>>();
    emb_kernel<<<NPOS, 96>>>();

    // pos = emb @ Wrel   [4095 x 512]  (f32x2)
    {
        float* posp = nullptr; cudaGetSymbolAddress((void**)&posp, g_pos);
        float* embp = nullptr; cudaGetSymbolAddress((void**)&embp, g_emb);
        gemm128_kernel<<<dim3(HD / 128, (NPOS + 127) / 128), 256>>>(
            embp, Wrel, posp, NPOS, HD, NRPF);
    }

    // prep: splits + weight transposes
    split_x_kernel<<<(BN * DIMM) / 1024, 256>>>(x);
    {
        __nv_bfloat16 *wth, *wtl, *woth, *wotl;
        cudaGetSymbolAddress((void**)&wth, g_wth);
        cudaGetSymbolAddress((void**)&wtl, g_wtl);
        cudaGetSymbolAddress((void**)&woth, g_woth);
        cudaGetSymbolAddress((void**)&wotl, g_wotl);
        dim3 tb2(32, 8);
        wtrans_kernel<<<dim3(HD / 32, DIMM / 32), tb2>>>(Wq, wth, wtl, DIMM, HD);
        wtrans_kernel<<<dim3(HD / 32, DIMM / 32), tb2>>>(Wk, wth + (size_t)HD * DIMM, wtl + (size_t)HD * DIMM, DIMM, HD);
        wtrans_kernel<<<dim3(HD / 32, DIMM / 32), tb2>>>(Wv, wth + (size_t)2 * HD * DIMM, wtl + (size_t)2 * HD * DIMM, DIMM, HD);
        wtrans_kernel<<<dim3(DIMM / 32, HD / 32), tb2>>>(Wo, woth, wotl, HD, DIMM);
    }

    // QKV projections (wmma tensor cores)
    qkv_wmma_kernel<<<dim3(HD / 128, BN / 128, 3), 256, GEMM_SMEM>>>(cb, pb);

    // fused content + relative logits (f32x2)
    logits_kernel<<<dim3(NSEQ / 128, NSEQ / 128, BB * HH), 256, LOGITS_SMEM>>>();

    // softmax -> split probs
    softmax_kernel<<<BB * HH * NSEQ, 128>>>();

    // attn @ v (wmma)
    av_wmma_kernel<<<dim3(NSEQ / 128, BB * HH), 256, AV_SMEM>>>();

    // final projection + bias (wmma)
    proj_wmma_kernel<<<dim3(DIMM / 128, BN / 128), 256, GEMM_SMEM>>>(out, bo);
}

// round 8
// speedup vs baseline: 2.1073x; 1.0318x over previous
#include <cuda_runtime.h>
#include <cuda_bf16.h>
#include <mma.h>
#include <cstdint>
#include <math.h>

using namespace nvcuda;

#define BB   2
#define NSEQ 2048
#define DIMM 1536
#define HH   8
#define DKK  64
#define DVV  64
#define NRPF 192
#define NB   32
#define NPOS 4095          // 2N-1
#define BN   4096          // B*N
#define HD   512           // H*DK

typedef unsigned long long ull;

// -------- scratch (device globals; no allocation allowed) --------
__device__ float g_p[NPOS * NB];
__device__ float g_pmax;
__device__ float g_emb[NPOS * NRPF];
__device__ float g_logits[(size_t)BB * HH * NSEQ * NSEQ];      // 268 MB
// bf16 split operands
__device__ __nv_bfloat16 g_xh[(size_t)BN * DIMM];
__device__ __nv_bfloat16 g_xl[(size_t)BN * DIMM];
__device__ __nv_bfloat16 g_wth[(size_t)3 * HD * DIMM];          // Wq/Wk/Wv transposed [z][512][1536]
__device__ __nv_bfloat16 g_wtl[(size_t)3 * HD * DIMM];
__device__ __nv_bfloat16 g_woth[(size_t)DIMM * HD];             // Wo^T [1536][512]
__device__ __nv_bfloat16 g_wotl[(size_t)DIMM * HD];
__device__ __nv_bfloat16 g_vth[(size_t)BB * HH * DVV * NSEQ];   // v^T per bh: [16][64][2048]
__device__ __nv_bfloat16 g_vtl[(size_t)BB * HH * DVV * NSEQ];
__device__ __nv_bfloat16 g_ph[(size_t)BB * HH * NSEQ * NSEQ];   // probs split
__device__ __nv_bfloat16 g_pl[(size_t)BB * HH * NSEQ * NSEQ];
__device__ __nv_bfloat16 g_aoh[(size_t)BN * HD];
__device__ __nv_bfloat16 g_aol[(size_t)BN * HD];
// split q/k/pos for wmma logits
__device__ __nv_bfloat16 g_qch[(size_t)BB * HH * NSEQ * DKK];
__device__ __nv_bfloat16 g_qcl[(size_t)BB * HH * NSEQ * DKK];
__device__ __nv_bfloat16 g_qph[(size_t)BB * HH * NSEQ * DKK];
__device__ __nv_bfloat16 g_qpl[(size_t)BB * HH * NSEQ * DKK];
__device__ __nv_bfloat16 g_kh [(size_t)BB * HH * NSEQ * DKK];
__device__ __nv_bfloat16 g_kl [(size_t)BB * HH * NSEQ * DKK];
__device__ __nv_bfloat16 g_posh[(size_t)NPOS * HD];
__device__ __nv_bfloat16 g_posl[(size_t)NPOS * HD];

// ---------------- f32x2 helpers (pos projection) ----------------
__device__ __forceinline__ ull dup2f(float a) {
    ull r; unsigned ai = __float_as_uint(a);
    asm("mov.b64 %0, {%1, %1};" : "=l"(r) : "r"(ai));
    return r;
}
__device__ __forceinline__ void fma2(ull &c, ull a, ull b) {
    asm("fma.rn.f32x2 %0, %1, %2, %0;" : "+l"(c) : "l"(a), "l"(b));
}
__device__ __forceinline__ void split2(float f, __nv_bfloat16 &h, __nv_bfloat16 &l) {
    h = __float2bfloat16(f);
    l = __float2bfloat16(f - __bfloat162float(h));
}

// ---------------- positional basis ----------------
__global__ void init_kernel() { g_pmax = 0.0f; }

__global__ void gamma_kernel() {
    int idx = blockIdx.x * blockDim.x + threadIdx.x;
    float p = 0.0f;
    if (idx < NPOS * NB) {
        int row = idx / NB;
        int j   = idx - row * NB;
        double ad   = (double)abs(row - (NSEQ - 1));
        double mean = 64.0 * (double)(j + 1);
        double conc = (mean / 32.0) * (mean / 32.0);
        double rate = mean / 1024.0;
        double xl   = (ad > 0.0) ? (conc - 1.0) * log(ad) : 0.0;
        double logp = xl - rate * ad - (lgamma(conc) - conc * log(rate));
        p = (float)exp(logp) + 1e-8f;
        g_p[idx] = p;
    }
    __shared__ float red[256];
    red[threadIdx.x] = p;
    __syncthreads();
    for (int s = 128; s > 0; s >>= 1) {
        if (threadIdx.x < s) red[threadIdx.x] = fmaxf(red[threadIdx.x], red[threadIdx.x + s]);
        __syncthreads();
    }
    if (threadIdx.x == 0) atomicMax((int*)&g_pmax, __float_as_int(red[0]));
}

__global__ void emb_kernel() {
    int row = blockIdx.x;
    int t   = threadIdx.x;
    int d   = row - (NSEQ - 1);
    float ad = fabsf((float)d);
    float sg = (d > 0) ? 1.0f : ((d < 0) ? -1.0f : 0.0f);
    float f;
    if (t < NB) {
        double maxr = log((double)NSEQ) / log(2.0);
        double xh   = 3.0 + (double)t * (maxr - 3.0) / (double)(NB - 1);
        double hl   = exp2(xh);
        f = (float)exp(-0.6931471805599453 / hl * (double)ad);
    } else if (t < 2 * NB) {
        int jj = t - NB;
        float width = exp2f((float)(jj + 1)) - 1.0f;
        f = (width > ad) ? 1.0f : 0.0f;
    } else {
        f = g_p[row * NB + (t - 2 * NB)] / g_pmax;
    }
    g_emb[row * NRPF + t]      = f;
    g_emb[row * NRPF + 96 + t] = sg * f;
}

// ---------------- f32x2 GEMM: pos = emb @ Wrel, epilogue -> split bf16 ----------------
__global__ __launch_bounds__(256, 2) void gemm128_kernel(
    const float* __restrict__ A, const float* __restrict__ B,
    int M, int N, int K)
{
    __shared__ float As[16 * 132];
    __shared__ float Bs[16 * 132];
    int tid = threadIdx.x;
    int tx = tid & 15, ty = tid >> 4;
    int j0 = blockIdx.x * 128, i0 = blockIdx.y * 128;
    ull acc[8][4] = {};
    for (int k0 = 0; k0 < K; k0 += 16) {
#pragma unroll
        for (int t = 0; t < 2; t++) {
            int idx = tid + t * 256;
            int r = idx >> 2, c4 = (idx & 3) * 4;
            float4 v = make_float4(0.f, 0.f, 0.f, 0.f);
            if (i0 + r < M) v = *(const float4*)&A[(size_t)(i0 + r) * K + k0 + c4];
            As[(c4 + 0) * 132 + r] = v.x; As[(c4 + 1) * 132 + r] = v.y;
            As[(c4 + 2) * 132 + r] = v.z; As[(c4 + 3) * 132 + r] = v.w;
        }
#pragma unroll
        for (int t = 0; t < 2; t++) {
            int idx = tid + t * 256;
            int r = idx >> 5, c4 = (idx & 31) * 4;
            *(float4*)&Bs[r * 132 + c4] = *(const float4*)&B[(size_t)(k0 + r) * N + j0 + c4];
        }
        __syncthreads();
#pragma unroll 4
        for (int kk = 0; kk < 16; kk++) {
            float4 a0 = *(float4*)&As[kk * 132 + ty * 8];
            float4 a1 = *(float4*)&As[kk * 132 + ty * 8 + 4];
            ulonglong2 b0 = *(ulonglong2*)&Bs[kk * 132 + tx * 8];
            ulonglong2 b1 = *(ulonglong2*)&Bs[kk * 132 + tx * 8 + 4];
            ull bp[4] = {b0.x, b0.y, b1.x, b1.y};
            float av[8] = {a0.x, a0.y, a0.z, a0.w, a1.x, a1.y, a1.z, a1.w};
#pragma unroll
            for (int ii = 0; ii < 8; ii++) {
                ull ad = dup2f(av[ii]);
#pragma unroll
                for (int jp = 0; jp < 4; jp++) fma2(acc[ii][jp], ad, bp[jp]);
            }
        }
        __syncthreads();
    }
#pragma unroll
    for (int ii = 0; ii < 8; ii++) {
        int gr = i0 + ty * 8 + ii;
        if (gr >= M) continue;
#pragma unroll
        for (int jp = 0; jp < 4; jp++) {
            int gc = j0 + tx * 8 + 2 * jp;
            ull v = acc[ii][jp];
            unsigned lo, hi;
            asm("mov.b64 {%0, %1}, %2;" : "=r"(lo), "=r"(hi) : "l"(v));
            __nv_bfloat16 h0, l0, h1, l1;
            split2(__uint_as_float(lo), h0, l0);
            split2(__uint_as_float(hi), h1, l1);
            size_t off = (size_t)gr * N + gc;
            *(__nv_bfloat162*)&g_posh[off] = __halves2bfloat162(h0, h1);
            *(__nv_bfloat162*)&g_posl[off] = __halves2bfloat162(l0, l1);
        }
    }
}

// ---------------- prep: split x into bf16 hi/lo ----------------
__global__ void split_x_kernel(const float* __restrict__ x) {
    size_t i = ((size_t)blockIdx.x * 256 + threadIdx.x) * 4;
    float4 v = *(const float4*)(x + i);
    __nv_bfloat16 h0, l0, h1, l1, h2, l2, h3, l3;
    split2(v.x, h0, l0); split2(v.y, h1, l1);
    split2(v.z, h2, l2); split2(v.w, h3, l3);
    *(__nv_bfloat162*)(g_xh + i)     = __halves2bfloat162(h0, h1);
    *(__nv_bfloat162*)(g_xh + i + 2) = __halves2bfloat162(h2, h3);
    *(__nv_bfloat162*)(g_xl + i)     = __halves2bfloat162(l0, l1);
    *(__nv_bfloat162*)(g_xl + i + 2) = __halves2bfloat162(l2, l3);
}

// ---------------- prep: transpose + split weight [K,N] -> [N,K] ----------------
__global__ void wtrans_kernel(const float* __restrict__ src,
                              __nv_bfloat16* __restrict__ dh, __nv_bfloat16* __restrict__ dl,
                              int K, int N) {
    __shared__ float t[32][33];
    int n0 = blockIdx.x * 32, k0 = blockIdx.y * 32;
    int tx = threadIdx.x, ty = threadIdx.y;   // 32 x 8
#pragma unroll
    for (int r = 0; r < 4; r++)
        t[ty + r * 8][tx] = src[(size_t)(k0 + ty + r * 8) * N + n0 + tx];
    __syncthreads();
#pragma unroll
    for (int r = 0; r < 4; r++) {
        int n = n0 + ty + r * 8;
        float v = t[tx][ty + r * 8];
        __nv_bfloat16 h, l; split2(v, h, l);
        dh[(size_t)n * K + k0 + tx] = h;
        dl[(size_t)n * K + k0 + tx] = l;
    }
}

// ================= wmma GEMM kernels (bf16x3 split, fp32 accum) ==========
#define GSTAGE_LD 48
#define GEMM_SMEM 67584

typedef wmma::fragment<wmma::matrix_a, 16, 16, 16, __nv_bfloat16, wmma::row_major> FragA;
typedef wmma::fragment<wmma::matrix_b, 16, 16, 16, __nv_bfloat16, wmma::col_major> FragB;
typedef wmma::fragment<wmma::accumulator, 16, 16, 16, float> FragC;

// generic 128x128xK mainloop: returns with C_s (f32, ldm 132) filled
__device__ __forceinline__ void wmma_main_128x128(
    char* sm, int tid,
    const __nv_bfloat16* Ah_g, const __nv_bfloat16* Al_g,   // rows i0.., stride K
    const __nv_bfloat16* Bh_g, const __nv_bfloat16* Bl_g,   // rows j0.., stride K
    int K)
{
    __nv_bfloat16* Ah_s = (__nv_bfloat16*)sm;
    __nv_bfloat16* Al_s = Ah_s + 128 * GSTAGE_LD;
    __nv_bfloat16* Bh_s = Al_s + 128 * GSTAGE_LD;
    __nv_bfloat16* Bl_s = Bh_s + 128 * GSTAGE_LD;
    int wid = tid >> 5;
    int wrow = wid >> 1, wcol = wid & 1;

    FragC acc[2][4];
#pragma unroll
    for (int m = 0; m < 2; m++)
#pragma unroll
        for (int n = 0; n < 4; n++) wmma::fill_fragment(acc[m][n], 0.0f);

    for (int kc = 0; kc < K; kc += 32) {
        __syncthreads();
#pragma unroll
        for (int t = 0; t < 2; t++) {
            int idx = tid + t * 256;
            int r = idx >> 2, c8 = (idx & 3) * 8;
            *(uint4*)&Ah_s[r * GSTAGE_LD + c8] = *(const uint4*)&Ah_g[(size_t)r * K + kc + c8];
            *(uint4*)&Al_s[r * GSTAGE_LD + c8] = *(const uint4*)&Al_g[(size_t)r * K + kc + c8];
            *(uint4*)&Bh_s[r * GSTAGE_LD + c8] = *(const uint4*)&Bh_g[(size_t)r * K + kc + c8];
            *(uint4*)&Bl_s[r * GSTAGE_LD + c8] = *(const uint4*)&Bl_g[(size_t)r * K + kc + c8];
        }
        __syncthreads();
#pragma unroll
        for (int kk = 0; kk < 32; kk += 16) {
            FragA fah[2], fal[2];
            FragB fbh[4], fbl[4];
#pragma unroll
            for (int m = 0; m < 2; m++) {
                wmma::load_matrix_sync(fah[m], Ah_s + (wrow * 32 + m * 16) * GSTAGE_LD + kk, GSTAGE_LD);
                wmma::load_matrix_sync(fal[m], Al_s + (wrow * 32 + m * 16) * GSTAGE_LD + kk, GSTAGE_LD);
            }
#pragma unroll
            for (int n = 0; n < 4; n++) {
                wmma::load_matrix_sync(fbh[n], Bh_s + (wcol * 64 + n * 16) * GSTAGE_LD + kk, GSTAGE_LD);
                wmma::load_matrix_sync(fbl[n], Bl_s + (wcol * 64 + n * 16) * GSTAGE_LD + kk, GSTAGE_LD);
            }
#pragma unroll
            for (int m = 0; m < 2; m++)
#pragma unroll
                for (int n = 0; n < 4; n++) {
                    wmma::mma_sync(acc[m][n], fah[m], fbh[n], acc[m][n]);
                    wmma::mma_sync(acc[m][n], fah[m], fbl[n], acc[m][n]);
                    wmma::mma_sync(acc[m][n], fal[m], fbh[n], acc[m][n]);
                }
        }
    }
    __syncthreads();
    float* C_s = (float*)sm;
#pragma unroll
    for (int m = 0; m < 2; m++)
#pragma unroll
        for (int n = 0; n < 4; n++)
            wmma::store_matrix_sync(C_s + (wrow * 32 + m * 16) * 132 + wcol * 64 + n * 16,
                                    acc[m][n], 132, wmma::mem_row_major);
    __syncthreads();
}

// ---- QKV: M=128 (bn), N=128 (hd), K=1536. z: 0=Q, 1=K, 2=V ----
__global__ __launch_bounds__(256, 2) void qkv_wmma_kernel(
    const float* __restrict__ cb, const float* __restrict__ pb)
{
    extern __shared__ char sm[];
    int tid = threadIdx.x;
    int z = blockIdx.z;
    int i0 = blockIdx.y * 128, j0 = blockIdx.x * 128;
    wmma_main_128x128(sm, tid,
        g_xh + (size_t)i0 * DIMM, g_xl + (size_t)i0 * DIMM,
        g_wth + (size_t)z * HD * DIMM + (size_t)j0 * DIMM,
        g_wtl + (size_t)z * HD * DIMM + (size_t)j0 * DIMM, DIMM);
    float* C_s = (float*)sm;

    if (z == 0) {
        for (int e = tid; e < 128 * 128; e += 256) {
            int r = e >> 7, c = e & 127;
            float val = C_s[r * 132 + c];
            int gr = i0 + r, gc = j0 + c;
            int b = gr >> 11, n = gr & 2047;
            int h = gc >> 6, dk = gc & 63;
            size_t off = (((size_t)(b * HH + h)) * NSEQ + n) * DKK + dk;
            float q = val * 0.125f;
            __nv_bfloat16 hh_, ll_;
            split2(q + cb[gc], hh_, ll_);
            g_qch[off] = hh_; g_qcl[off] = ll_;
            split2(q + pb[gc], hh_, ll_);
            g_qph[off] = hh_; g_qpl[off] = ll_;
        }
    } else if (z == 1) {
        for (int e = tid; e < 128 * 128; e += 256) {
            int r = e >> 7, c = e & 127;
            int gr = i0 + r, gc = j0 + c;
            int b = gr >> 11, n = gr & 2047;
            int h = gc >> 6, dk = gc & 63;
            size_t off = (((size_t)(b * HH + h)) * NSEQ + n) * DKK + dk;
            __nv_bfloat16 hh_, ll_;
            split2(C_s[r * 132 + c], hh_, ll_);
            g_kh[off] = hh_; g_kl[off] = ll_;
        }
    } else {
        for (int e = tid; e < 128 * 128; e += 256) {
            int r = e & 127, c = e >> 7;        // column-major walk: coalesced on n
            float val = C_s[r * 132 + c];
            int gr = i0 + r, gc = j0 + c;
            int b = gr >> 11, n = gr & 2047;
            int h = gc >> 6, dk = gc & 63;
            __nv_bfloat16 hh_, ll_;
            split2(val, hh_, ll_);
            size_t off = (((size_t)(b * HH + h)) * DVV + dk) * NSEQ + n;
            g_vth[off] = hh_; g_vtl[off] = ll_;
        }
    }
}

// ---- final projection: M=128 (bn), N=128 (dim), K=512 ----
__global__ __launch_bounds__(256, 2) void proj_wmma_kernel(
    float* __restrict__ out, const float* __restrict__ bo)
{
    extern __shared__ char sm[];
    int tid = threadIdx.x;
    int i0 = blockIdx.y * 128, j0 = blockIdx.x * 128;
    wmma_main_128x128(sm, tid,
        g_aoh + (size_t)i0 * HD, g_aol + (size_t)i0 * HD,
        g_woth + (size_t)j0 * HD, g_wotl + (size_t)j0 * HD, HD);
    float* C_s = (float*)sm;
    for (int e = tid; e < 128 * 128; e += 256) {
        int r = e >> 7, c = e & 127;
        out[(size_t)(i0 + r) * DIMM + j0 + c] = C_s[r * 132 + c] + bo[j0 + c];
    }
}

// ---- attn@V: per bh, M=128 (i), N=64 (d), K=2048 ----
#define AV_SMEM 36864
__global__ __launch_bounds__(256, 2) void av_wmma_kernel()
{
    extern __shared__ char sm[];
    int tid = threadIdx.x, wid = tid >> 5;
    int bh = blockIdx.y;
    int i0 = blockIdx.x * 128;
    const __nv_bfloat16* Ah_g = g_ph + (size_t)bh * NSEQ * NSEQ + (size_t)i0 * NSEQ;
    const __nv_bfloat16* Al_g = g_pl + (size_t)bh * NSEQ * NSEQ + (size_t)i0 * NSEQ;
    const __nv_bfloat16* Bh_g = g_vth + (size_t)bh * DVV * NSEQ;
    const __nv_bfloat16* Bl_g = g_vtl + (size_t)bh * DVV * NSEQ;

    __nv_bfloat16* Ah_s = (__nv_bfloat16*)sm;
    __nv_bfloat16* Al_s = Ah_s + 128 * GSTAGE_LD;
    __nv_bfloat16* Bh_s = Al_s + 128 * GSTAGE_LD;
    __nv_bfloat16* Bl_s = Bh_s + 64 * GSTAGE_LD;

    FragC acc[4];
#pragma unroll
    for (int n = 0; n < 4; n++) wmma::fill_fragment(acc[n], 0.0f);

    for (int kc = 0; kc < NSEQ; kc += 32) {
        __syncthreads();
#pragma unroll
        for (int t = 0; t < 2; t++) {
            int idx = tid + t * 256;
            int r = idx >> 2, c8 = (idx & 3) * 8;
            *(uint4*)&Ah_s[r * GSTAGE_LD + c8] = *(const uint4*)&Ah_g[(size_t)r * NSEQ + kc + c8];
            *(uint4*)&Al_s[r * GSTAGE_LD + c8] = *(const uint4*)&Al_g[(size_t)r * NSEQ + kc + c8];
        }
        {
            int r = tid >> 2, c8 = (tid & 3) * 8;
            if (r < 64) {
                *(uint4*)&Bh_s[r * GSTAGE_LD + c8] = *(const uint4*)&Bh_g[(size_t)r * NSEQ + kc + c8];
                *(uint4*)&Bl_s[r * GSTAGE_LD + c8] = *(const uint4*)&Bl_g[(size_t)r * NSEQ + kc + c8];
            }
        }
        __syncthreads();
#pragma unroll
        for (int kk = 0; kk < 32; kk += 16) {
            FragA fah, fal;
            FragB fbh[4], fbl[4];
            wmma::load_matrix_sync(fah, Ah_s + (wid * 16) * GSTAGE_LD + kk, GSTAGE_LD);
            wmma::load_matrix_sync(fal, Al_s + (wid * 16) * GSTAGE_LD + kk, GSTAGE_LD);
#pragma unroll
            for (int n = 0; n < 4; n++) {
                wmma::load_matrix_sync(fbh[n], Bh_s + (n * 16) * GSTAGE_LD + kk, GSTAGE_LD);
                wmma::load_matrix_sync(fbl[n], Bl_s + (n * 16) * GSTAGE_LD + kk, GSTAGE_LD);
            }
#pragma unroll
            for (int n = 0; n < 4; n++) {
                wmma::mma_sync(acc[n], fah, fbh[n], acc[n]);
                wmma::mma_sync(acc[n], fah, fbl[n], acc[n]);
                wmma::mma_sync(acc[n], fal, fbh[n], acc[n]);
            }
        }
    }
    __syncthreads();
    float* C_s = (float*)sm;   // 128 x 68
#pragma unroll
    for (int n = 0; n < 4; n++)
        wmma::store_matrix_sync(C_s + (wid * 16) * 68 + n * 16, acc[n], 68, wmma::mem_row_major);
    __syncthreads();

    int b = bh >> 3, h = bh & 7;
    for (int e = tid; e < 128 * 64; e += 256) {
        int r = e >> 6, c = e & 63;
        float val = C_s[r * 68 + c];
        int n = i0 + r;
        __nv_bfloat16 hh_, ll_;
        split2(val, hh_, ll_);
        size_t off = ((size_t)(b * NSEQ + n)) * HD + h * 64 + c;
        g_aoh[off] = hh_; g_aol[off] = ll_;
    }
}

// ================= wmma logits: content + shifted relative =================
// smem: staging 4 x [128 x 48] bf16 (49152 B) then C/T region 128x132 f32 (67584 B)
#define LG_STAGE_BYTES (4 * 128 * GSTAGE_LD * 2)
#define LG_SMEM (LG_STAGE_BYTES + 128 * 132 * 4)     // 116736

// 128x128x64 GEMM (bf16x3) -> C region. B rows clamped at maxr (for pos band edge).
__device__ __forceinline__ void lg_gemm_store(
    char* sm, int tid,
    const __nv_bfloat16* __restrict__ Ah_g, const __nv_bfloat16* __restrict__ Al_g,
    const __nv_bfloat16* __restrict__ Bh_g, const __nv_bfloat16* __restrict__ Bl_g,
    size_t bstride, int maxr)
{
    __nv_bfloat16* Ah_s = (__nv_bfloat16*)sm;
    __nv_bfloat16* Al_s = Ah_s + 128 * GSTAGE_LD;
    __nv_bfloat16* Bh_s = Al_s + 128 * GSTAGE_LD;
    __nv_bfloat16* Bl_s = Bh_s + 128 * GSTAGE_LD;
    int wid = tid >> 5;
    int wrow = wid >> 1, wcol = wid & 1;

    FragC acc[2][4];
#pragma unroll
    for (int m = 0; m < 2; m++)
#pragma unroll
        for (int n = 0; n < 4; n++) wmma::fill_fragment(acc[m][n], 0.0f);

    for (int kc = 0; kc < 64; kc += 32) {
        __syncthreads();
#pragma unroll
        for (int t = 0; t < 2; t++) {
            int idx = tid + t * 256;
            int r = idx >> 2, c8 = (idx & 3) * 8;
            *(uint4*)&Ah_s[r * GSTAGE_LD + c8] = *(const uint4*)&Ah_g[(size_t)r * 64 + kc + c8];
            *(uint4*)&Al_s[r * GSTAGE_LD + c8] = *(const uint4*)&Al_g[(size_t)r * 64 + kc + c8];
            int br = (r < maxr) ? r : maxr;
            *(uint4*)&Bh_s[r * GSTAGE_LD + c8] = *(const uint4*)&Bh_g[(size_t)br * bstride + kc + c8];
            *(uint4*)&Bl_s[r * GSTAGE_LD + c8] = *(const uint4*)&Bl_g[(size_t)br * bstride + kc + c8];
        }
        __syncthreads();
#pragma unroll
        for (int kk = 0; kk < 32; kk += 16) {
            FragA fah[2], fal[2];
            FragB fbh[4], fbl[4];
#pragma unroll
            for (int m = 0; m < 2; m++) {
                wmma::load_matrix_sync(fah[m], Ah_s + (wrow * 32 + m * 16) * GSTAGE_LD + kk, GSTAGE_LD);
                wmma::load_matrix_sync(fal[m], Al_s + (wrow * 32 + m * 16) * GSTAGE_LD + kk, GSTAGE_LD);
            }
#pragma unroll
            for (int n = 0; n < 4; n++) {
                wmma::load_matrix_sync(fbh[n], Bh_s + (wcol * 64 + n * 16) * GSTAGE_LD + kk, GSTAGE_LD);
                wmma::load_matrix_sync(fbl[n], Bl_s + (wcol * 64 + n * 16) * GSTAGE_LD + kk, GSTAGE_LD);
            }
#pragma unroll
            for (int m = 0; m < 2; m++)
#pragma unroll
                for (int n = 0; n < 4; n++) {
                    wmma::mma_sync(acc[m][n], fah[m], fbh[n], acc[m][n]);
                    wmma::mma_sync(acc[m][n], fah[m], fbl[n], acc[m][n]);
                    wmma::mma_sync(acc[m][n], fal[m], fbh[n], acc[m][n]);
                }
        }
    }
    float* C_s = (float*)(sm + LG_STAGE_BYTES);
#pragma unroll
    for (int m = 0; m < 2; m++)
#pragma unroll
        for (int n = 0; n < 4; n++)
            wmma::store_matrix_sync(C_s + (wrow * 32 + m * 16) * 132 + wcol * 64 + n * 16,
                                    acc[m][n], 132, wmma::mem_row_major);
    __syncthreads();
}

__global__ __launch_bounds__(256, 1) void logits_wmma_kernel()
{
    extern __shared__ char sm[];
    int tid = threadIdx.x;
    int bh = blockIdx.z, h = bh & 7;
    int i0 = blockIdx.y * 128, j0 = blockIdx.x * 128;
    float* C_s = (float*)(sm + LG_STAGE_BYTES);

    size_t abase = ((size_t)bh * NSEQ + i0) * DKK;
    size_t kbase = ((size_t)bh * NSEQ + j0) * DKK;

    // Phase A: content = qc . k
    lg_gemm_store(sm, tid, g_qch + abase, g_qcl + abase,
                  g_kh + kbase, g_kl + kbase, DKK, 127);

    // each thread owns row ro = tid>>1, 64 cols starting at cb
    int ro = tid >> 1, cb = (tid & 1) * 64;
    float v[64];
#pragma unroll
    for (int c = 0; c < 64; c += 4) {
        float4 t4 = *(float4*)&C_s[ro * 132 + cb + c];
        v[c] = t4.x; v[c + 1] = t4.y; v[c + 2] = t4.z; v[c + 3] = t4.w;
    }
    __syncthreads();

    // Phase B: rel via T[i'][r] = qp . pos_band, gathered at r = j'-i'+127
    int rbase = (NSEQ - 1) + j0 - i0 - 127;
#pragma unroll
    for (int ch = 0; ch < 2; ch++) {
        int r0 = rbase + 128 * ch;
        lg_gemm_store(sm, tid, g_qph + abase, g_qpl + abase,
                      g_posh + (size_t)r0 * HD + h * 64,
                      g_posl + (size_t)r0 * HD + h * 64,
                      HD, (NPOS - 1) - r0);
        int base_rl = cb - ro + 127 - 128 * ch;
#pragma unroll
        for (int c = 0; c < 64; c++) {
            int rl = base_rl + c;
            if (rl >= 0 && rl < 128) v[c] += C_s[ro * 132 + rl];
        }
        __syncthreads();
    }

    // write
    size_t ob = ((size_t)bh * NSEQ + i0 + ro) * NSEQ + j0 + cb;
#pragma unroll
    for (int c = 0; c < 64; c += 4)
        *(float4*)&g_logits[ob + c] = make_float4(v[c], v[c + 1], v[c + 2], v[c + 3]);
}

// ---------------- softmax -> bf16 hi/lo probs ----------------
__global__ __launch_bounds__(128) void softmax_kernel() {
    size_t row = blockIdx.x;
    const float* p = g_logits + row * NSEQ;
    int tid = threadIdx.x;
    float4 v[4];
    float m = -1e30f;
#pragma unroll
    for (int e = 0; e < 4; e++) {
        v[e] = *(const float4*)&p[tid * 4 + e * 512];
        m = fmaxf(m, fmaxf(fmaxf(v[e].x, v[e].y), fmaxf(v[e].z, v[e].w)));
    }
    __shared__ float red[128];
    red[tid] = m; __syncthreads();
    for (int s = 64; s > 0; s >>= 1) {
        if (tid < s) red[tid] = fmaxf(red[tid], red[tid + s]);
        __syncthreads();
    }
    m = red[0]; __syncthreads();
    float sum = 0.f;
#pragma unroll
    for (int e = 0; e < 4; e++) {
        v[e].x = __expf(v[e].x - m); v[e].y = __expf(v[e].y - m);
        v[e].z = __expf(v[e].z - m); v[e].w = __expf(v[e].w - m);
        sum += v[e].x + v[e].y + v[e].z + v[e].w;
    }
    red[tid] = sum; __syncthreads();
    for (int s = 64; s > 0; s >>= 1) {
        if (tid < s) red[tid] += red[tid + s];
        __syncthreads();
    }
    float inv = 1.0f / red[0];
    __nv_bfloat16* ph = g_ph + row * NSEQ;
    __nv_bfloat16* pl = g_pl + row * NSEQ;
#pragma unroll
    for (int e = 0; e < 4; e++) {
        float p0 = v[e].x * inv, p1 = v[e].y * inv, p2 = v[e].z * inv, p3 = v[e].w * inv;
        __nv_bfloat16 h0, l0, h1, l1, h2, l2, h3, l3;
        split2(p0, h0, l0); split2(p1, h1, l1); split2(p2, h2, l2); split2(p3, h3, l3);
        int base = tid * 4 + e * 512;
        *(__nv_bfloat162*)&ph[base]     = __halves2bfloat162(h0, h1);
        *(__nv_bfloat162*)&ph[base + 2] = __halves2bfloat162(h2, h3);
        *(__nv_bfloat162*)&pl[base]     = __halves2bfloat162(l0, l1);
        *(__nv_bfloat162*)&pl[base + 2] = __halves2bfloat162(l2, l3);
    }
}

// ---------------- launch ----------------
extern "C" void kernel_launch(void* const* d_in, const int* in_sizes, int n_in,
                              void* d_out, int out_size) {
    const float* x    = (const float*)d_in[0];
    const float* Wq   = (const float*)d_in[1];
    const float* Wk   = (const float*)d_in[2];
    const float* Wv   = (const float*)d_in[3];
    const float* Wo   = (const float*)d_in[4];
    const float* bo   = (const float*)d_in[5];
    const float* Wrel = (const float*)d_in[6];
    const float* cb   = (const float*)d_in[7];
    const float* pb   = (const float*)d_in[8];
    float* out = (float*)d_out;

    cudaFuncSetAttribute(qkv_wmma_kernel, cudaFuncAttributeMaxDynamicSharedMemorySize, GEMM_SMEM);
    cudaFuncSetAttribute(proj_wmma_kernel, cudaFuncAttributeMaxDynamicSharedMemorySize, GEMM_SMEM);
    cudaFuncSetAttribute(av_wmma_kernel, cudaFuncAttributeMaxDynamicSharedMemorySize, AV_SMEM);
    cudaFuncSetAttribute(logits_wmma_kernel, cudaFuncAttributeMaxDynamicSharedMemorySize, LG_SMEM);

    // positional basis
    init_kernel<<<1, 1>>>();
    gamma_kernel<<<(NPOS * NB + 255) / 256, 256>>>();
    emb_kernel<<<NPOS, 96>>>();

    // pos = emb @ Wrel  [4095 x 512] (f32x2, split-bf16 epilogue)
    {
        float* embp = nullptr; cudaGetSymbolAddress((void**)&embp, g_emb);
        gemm128_kernel<<<dim3(HD / 128, (NPOS + 127) / 128), 256>>>(
            embp, Wrel, NPOS, HD, NRPF);
    }

    // prep: splits + weight transposes
    split_x_kernel<<<(BN * DIMM) / 1024, 256>>>(x);
    {
        __nv_bfloat16 *wth, *wtl, *woth, *wotl;
        cudaGetSymbolAddress((void**)&wth, g_wth);
        cudaGetSymbolAddress((void**)&wtl, g_wtl);
        cudaGetSymbolAddress((void**)&woth, g_woth);
        cudaGetSymbolAddress((void**)&wotl, g_wotl);
        dim3 tb2(32, 8);
        wtrans_kernel<<<dim3(HD / 32, DIMM / 32), tb2>>>(Wq, wth, wtl, DIMM, HD);
        wtrans_kernel<<<dim3(HD / 32, DIMM / 32), tb2>>>(Wk, wth + (size_t)HD * DIMM, wtl + (size_t)HD * DIMM, DIMM, HD);
        wtrans_kernel<<<dim3(HD / 32, DIMM / 32), tb2>>>(Wv, wth + (size_t)2 * HD * DIMM, wtl + (size_t)2 * HD * DIMM, DIMM, HD);
        wtrans_kernel<<<dim3(DIMM / 32, HD / 32), tb2>>>(Wo, woth, wotl, HD, DIMM);
    }

    // QKV projections (wmma, split-bf16 epilogues)
    qkv_wmma_kernel<<<dim3(HD / 128, BN / 128, 3), 256, GEMM_SMEM>>>(cb, pb);

    // fused content + relative logits (wmma + shift-gather)
    logits_wmma_kernel<<<dim3(NSEQ / 128, NSEQ / 128, BB * HH), 256, LG_SMEM>>>();

    // softmax -> split probs
    softmax_kernel<<<BB * HH * NSEQ, 128>>>();

    // attn @ v (wmma)
    av_wmma_kernel<<<dim3(NSEQ / 128, BB * HH), 256, AV_SMEM>>>();

    // final projection + bias (wmma)
    proj_wmma_kernel<<<dim3(DIMM / 128, BN / 128), 256, GEMM_SMEM>>>(out, bo);
}